// round 8
// baseline (speedup 1.0000x reference)
#include <cuda_runtime.h>
#include <math.h>

// ---------------- problem constants ----------------
constexpr int NN   = 20000;
constexpr int EE   = 320000;
constexpr int NT   = 200000;
constexpr int IND  = 512;   // INPUT_DIM
constexpr int DC   = 256;
constexpr int HEADS = 8;

// ---------------- scratch (static device globals; no runtime alloc) --------
__device__ float g_W12[512 * 512];
__device__ float g_b12[512];
__device__ float g_Wtftg[256 * 256];
__device__ float g_btftg[256];
__device__ float g_Wab[128 * 128];
__device__ float g_bab[128];

__device__ float g_h[(size_t)NN * 512];    // [h_gcn1 | h_gcn2]
__device__ float g_dinv[NN];

// CSR structures for the edge gather
__device__ int g_deg[NN];
__device__ int g_cnt[NN];
__device__ int g_off[NN + 1];
__device__ int g_esrc[EE];

__device__ float g_g1[(size_t)NN * 256];   // sigmoid(gcn1)
__device__ float g_xa[(size_t)NN * 256];   // gcn2 raw
__device__ float g_xg[(size_t)NN * 128];
__device__ float g_tftg[(size_t)NN * 256]; // [tf | tg]

__device__ float g_kin[(size_t)NN * 128];  // tf + pos_emb lookup
__device__ float g_q[(size_t)NN * 128];    // xg @ Wq + bq (pos term added in attn)
__device__ float g_peq[512 * 128];         // pos_emb @ Wq

__device__ float g_kinc[DC * 128];         // Ek @ kin
__device__ float g_vinc[DC * 128];         // Ev @ tg
__device__ float g_rsk[DC];                // rowsum(Ek)
__device__ float g_rsv[DC];                // rowsum(Ev)
__device__ float g_kc[DC * 128];
__device__ float g_vc[DC * 128];

__device__ float g_att[(size_t)NN * 128];
__device__ float g_xf[(size_t)NN * 128];
__device__ float g_ab[(size_t)NN * 128];   // [tfa | tga], leaky applied
__device__ float g_na[NN];
__device__ float g_nb[NN];

// ---------------- packed f32x2 helpers ----------------
__device__ __forceinline__ unsigned long long pack_dup(float a) {
    unsigned long long r;
    unsigned u = __float_as_uint(a);
    asm("mov.b64 %0, {%1, %1};" : "=l"(r) : "r"(u));
    return r;
}
__device__ __forceinline__ float2 unpack64(unsigned long long v) {
    unsigned lo, hi;
    asm("mov.b64 {%0, %1}, %2;" : "=r"(lo), "=r"(hi) : "l"(v));
    float2 r;
    r.x = __uint_as_float(lo);
    r.y = __uint_as_float(hi);
    return r;
}
#define FMA2(acc, ap, bp) \
    asm("fma.rn.f32x2 %0, %1, %2, %0;" : "+l"(acc) : "l"(ap), "l"(bp))

// ---------------- small helpers ----------------
__global__ void zero_cc() {
    int i = blockIdx.x * blockDim.x + threadIdx.x;
    if (i < DC * 128) { g_kinc[i] = 0.0f; g_vinc[i] = 0.0f; }
}

// pack W = [W1 | W2] (rows x 2*hc), b = [b1 | b2]
__global__ void pack2(float* __restrict__ W, const float* __restrict__ W1,
                      const float* __restrict__ W2, float* __restrict__ b,
                      const float* __restrict__ b1, const float* __restrict__ b2,
                      int rows, int hc) {
    int idx = blockIdx.x * blockDim.x + threadIdx.x;
    int tot = rows * 2 * hc;
    if (idx < tot) {
        int r = idx / (2 * hc);
        int c = idx - r * 2 * hc;
        W[idx] = (c < hc) ? W1[r * hc + c] : W2[r * hc + (c - hc)];
    }
    if (idx < 2 * hc) b[idx] = (idx < hc) ? b1[idx] : b2[idx - hc];
}

// ---------------- CSR construction ----------------
__global__ void deg_zero() {
    int i = blockIdx.x * blockDim.x + threadIdx.x;
    if (i < NN) { g_deg[i] = 0; g_cnt[i] = 0; }
}
__global__ void deg_count(const int* __restrict__ adj) {
    int e = blockIdx.x * blockDim.x + threadIdx.x;
    if (e < EE) atomicAdd(&g_deg[adj[EE + e]], 1);
}
__global__ void __launch_bounds__(1024) scan_offsets() {
    __shared__ int partial[1024];
    const int tid = threadIdx.x;
    const int PER = (NN + 1023) / 1024;   // 20
    const int base = tid * PER;
    int s = 0;
#pragma unroll
    for (int i = 0; i < PER; i++) {
        int idx = base + i;
        if (idx < NN) s += g_deg[idx];
    }
    partial[tid] = s;
    __syncthreads();
    for (int off = 1; off < 1024; off <<= 1) {
        int v = 0;
        if (tid >= off) v = partial[tid - off];
        __syncthreads();
        if (tid >= off) partial[tid] += v;
        __syncthreads();
    }
    int run = (tid > 0) ? partial[tid - 1] : 0;
#pragma unroll
    for (int i = 0; i < PER; i++) {
        int idx = base + i;
        if (idx < NN) {
            g_off[idx] = run;
            int d = g_deg[idx];
            run += d;
            g_dinv[idx] = rsqrtf(1.0f + (float)d);
        }
    }
    if (tid == 0) g_off[NN] = EE;
}
__global__ void fill_csr(const int* __restrict__ adj) {
    int e = blockIdx.x * blockDim.x + threadIdx.x;
    if (e >= EE) return;
    int s = adj[e];
    int d = adj[EE + e];
    int pos = g_off[d] + atomicAdd(&g_cnt[d], 1);
    g_esrc[pos] = s;
}

// ---------------- row sums of Ek / Ev (for bias folding) -------------------
__global__ void rowsums(const float* __restrict__ Ek, const float* __restrict__ Ev) {
    int gw = (blockIdx.x * blockDim.x + threadIdx.x) >> 5;
    int lane = threadIdx.x & 31;
    if (gw >= 2 * DC) return;
    const float* src = (gw < DC) ? Ek + (size_t)gw * NN : Ev + (size_t)(gw - DC) * NN;
    float s = 0.0f;
    for (int i = lane * 4; i < NN; i += 128) {
        float4 v = *(const float4*)(src + i);
        s += v.x + v.y + v.z + v.w;
    }
#pragma unroll
    for (int o = 16; o > 0; o >>= 1) s += __shfl_xor_sync(0xffffffffu, s, o);
    if (lane == 0) {
        if (gw < DC) g_rsk[gw] = s;
        else         g_rsv[gw - DC] = s;
    }
}

// ---------------- CSR gather + fused GCN finalize --------------------------
__global__ void __launch_bounds__(128) gcn_gather() {
    __shared__ int   s_src[128];
    __shared__ float s_coef[128];
    const int d = blockIdx.x;
    const int tid = threadIdx.x;
    const int beg = g_off[d];
    const int deg = g_off[d + 1] - beg;
    const float di = g_dinv[d];

    float4 acc = {0.f, 0.f, 0.f, 0.f};
    for (int c0 = 0; c0 < deg; c0 += 128) {
        int m = min(128, deg - c0);
        if (tid < m) {
            int s = g_esrc[beg + c0 + tid];
            s_src[tid] = s;
            s_coef[tid] = g_dinv[s] * di;
        }
        __syncthreads();
        int i = 0;
#pragma unroll 1
        for (; i + 4 <= m; i += 4) {
            const float4 h0 = *(const float4*)(g_h + (size_t)s_src[i + 0] * 512 + tid * 4);
            const float4 h1 = *(const float4*)(g_h + (size_t)s_src[i + 1] * 512 + tid * 4);
            const float4 h2 = *(const float4*)(g_h + (size_t)s_src[i + 2] * 512 + tid * 4);
            const float4 h3 = *(const float4*)(g_h + (size_t)s_src[i + 3] * 512 + tid * 4);
            float c0f = s_coef[i + 0], c1f = s_coef[i + 1];
            float c2f = s_coef[i + 2], c3f = s_coef[i + 3];
            acc.x += h0.x * c0f; acc.y += h0.y * c0f; acc.z += h0.z * c0f; acc.w += h0.w * c0f;
            acc.x += h1.x * c1f; acc.y += h1.y * c1f; acc.z += h1.z * c1f; acc.w += h1.w * c1f;
            acc.x += h2.x * c2f; acc.y += h2.y * c2f; acc.z += h2.z * c2f; acc.w += h2.w * c2f;
            acc.x += h3.x * c3f; acc.y += h3.y * c3f; acc.z += h3.z * c3f; acc.w += h3.w * c3f;
        }
        for (; i < m; i++) {
            const float4 hv = *(const float4*)(g_h + (size_t)s_src[i] * 512 + tid * 4);
            float cf = s_coef[i];
            acc.x += hv.x * cf; acc.y += hv.y * cf; acc.z += hv.z * cf; acc.w += hv.w * cf;
        }
        __syncthreads();
    }

    const int j = tid * 4;
    const float4 hd = *(const float4*)(g_h + (size_t)d * 512 + j);
    const float4 bb = *(const float4*)(g_b12 + j);
    const float d2 = di * di;
    float4 v;
    v.x = acc.x + hd.x * d2 + bb.x;
    v.y = acc.y + hd.y * d2 + bb.y;
    v.z = acc.z + hd.z * d2 + bb.z;
    v.w = acc.w + hd.w * d2 + bb.w;
    if (j < 256) {
        float4 o;
        o.x = 1.0f / (1.0f + __expf(-v.x));
        o.y = 1.0f / (1.0f + __expf(-v.y));
        o.z = 1.0f / (1.0f + __expf(-v.z));
        o.w = 1.0f / (1.0f + __expf(-v.w));
        *(float4*)(g_g1 + (size_t)d * 256 + j) = o;
    } else {
        *(float4*)(g_xa + (size_t)d * 256 + (j - 256)) = v;
    }
}

// ---------------- kin = tf + pos_emb[positions] ----------------------------
__global__ void build_kin(const int* __restrict__ positions,
                          const float* __restrict__ pos_emb) {
    int idx = blockIdx.x * blockDim.x + threadIdx.x;
    if (idx >= NN * 128) return;
    int n = idx >> 7;
    int j = idx & 127;
    g_kin[idx] = g_tftg[(size_t)n * 256 + j] + pos_emb[positions[n] * 128 + j];
}

// ---------------- packed-f32x2 SGEMM: C = act(A@B + bias) ------------------
// BM=BN=128, BK=16, double-buffered smem, 256 threads, 8x8 per thread.
// ACT: 0 = none, 1 = leaky relu, 2 = C = A@B + rowscale[row]*bias[col]
template <int ACT>
__global__ void __launch_bounds__(256)
sgemm2(const float* __restrict__ A, const float* __restrict__ B,
       const float* __restrict__ bias, const float* __restrict__ rowscale,
       float* __restrict__ C, int M, int N, int K) {
    __shared__ float As[2][16][128];
    __shared__ float Bs[2][16][128];
    const int tid = threadIdx.x;
    const int rowBase = blockIdx.y * 128;
    const int colBase = blockIdx.x * 128;

    const int lr = tid >> 1;           // 0..127 A row
    const int lq = (tid & 1) * 8;      // 0 or 8 k-offset
    const int br = tid >> 5;           // 0..7 B k-row (and br+8)
    const int bc = (tid & 31) * 4;     // B col
    const int rm = tid >> 4;           // 0..15
    const int rn = tid & 15;           // 0..15

    const int arow = rowBase + lr;
    const bool aval = arow < M;
    const float* Aptr = A + (size_t)arow * K + lq;
    const float* Bptr = B + colBase + bc;

    unsigned long long acc[8][4];
#pragma unroll
    for (int i = 0; i < 8; i++)
#pragma unroll
        for (int j = 0; j < 4; j++) acc[i][j] = 0ULL;

    const int niter = K >> 4;
    float4 a0, a1, b0, b1;
    // preload iter 0
    a0 = aval ? *(const float4*)(Aptr + 0) : make_float4(0, 0, 0, 0);
    a1 = aval ? *(const float4*)(Aptr + 4) : make_float4(0, 0, 0, 0);
    b0 = *(const float4*)(Bptr + (size_t)br * N);
    b1 = *(const float4*)(Bptr + (size_t)(br + 8) * N);
    As[0][lq + 0][lr] = a0.x; As[0][lq + 1][lr] = a0.y;
    As[0][lq + 2][lr] = a0.z; As[0][lq + 3][lr] = a0.w;
    As[0][lq + 4][lr] = a1.x; As[0][lq + 5][lr] = a1.y;
    As[0][lq + 6][lr] = a1.z; As[0][lq + 7][lr] = a1.w;
    *(float4*)&Bs[0][br][bc] = b0;
    *(float4*)&Bs[0][br + 8][bc] = b1;
    __syncthreads();

    for (int it = 0; it < niter; it++) {
        const int cur = it & 1;
        if (it + 1 < niter) {
            const int k0 = (it + 1) << 4;
            a0 = aval ? *(const float4*)(Aptr + k0) : make_float4(0, 0, 0, 0);
            a1 = aval ? *(const float4*)(Aptr + k0 + 4) : make_float4(0, 0, 0, 0);
            b0 = *(const float4*)(Bptr + (size_t)(k0 + br) * N);
            b1 = *(const float4*)(Bptr + (size_t)(k0 + br + 8) * N);
        }
#pragma unroll
        for (int k = 0; k < 16; k++) {
            float4 av0 = *(const float4*)&As[cur][k][rm * 8];
            float4 av1 = *(const float4*)&As[cur][k][rm * 8 + 4];
            ulonglong2 bp0 = *(const ulonglong2*)&Bs[cur][k][rn * 8];
            ulonglong2 bp1 = *(const ulonglong2*)&Bs[cur][k][rn * 8 + 4];
            float av[8] = {av0.x, av0.y, av0.z, av0.w, av1.x, av1.y, av1.z, av1.w};
#pragma unroll
            for (int i = 0; i < 8; i++) {
                unsigned long long ap = pack_dup(av[i]);
                FMA2(acc[i][0], ap, bp0.x);
                FMA2(acc[i][1], ap, bp0.y);
                FMA2(acc[i][2], ap, bp1.x);
                FMA2(acc[i][3], ap, bp1.y);
            }
        }
        if (it + 1 < niter) {
            const int nxt = cur ^ 1;
            As[nxt][lq + 0][lr] = a0.x; As[nxt][lq + 1][lr] = a0.y;
            As[nxt][lq + 2][lr] = a0.z; As[nxt][lq + 3][lr] = a0.w;
            As[nxt][lq + 4][lr] = a1.x; As[nxt][lq + 5][lr] = a1.y;
            As[nxt][lq + 6][lr] = a1.z; As[nxt][lq + 7][lr] = a1.w;
            *(float4*)&Bs[nxt][br][bc] = b0;
            *(float4*)&Bs[nxt][br + 8][bc] = b1;
        }
        __syncthreads();
    }

#pragma unroll
    for (int i = 0; i < 8; i++) {
        int row = rowBase + rm * 8 + i;
        if (row >= M) continue;
        float rsc = (ACT == 2) ? rowscale[row] : 1.0f;
        float vals[8];
#pragma unroll
        for (int jp = 0; jp < 4; jp++) {
            float2 f = unpack64(acc[i][jp]);
            vals[2 * jp] = f.x;
            vals[2 * jp + 1] = f.y;
        }
        int col0 = colBase + rn * 8;
#pragma unroll
        for (int j4 = 0; j4 < 2; j4++) {
            float4 o;
            float* op = &o.x;
#pragma unroll
            for (int j = 0; j < 4; j++) {
                int jj = j4 * 4 + j;
                float v = vals[jj];
                if (bias) v += rsc * bias[col0 + jj];
                if (ACT == 1) v = (v >= 0.0f) ? v : 0.01f * v;
                op[j] = v;
            }
            *(float4*)&C[(size_t)row * N + col0 + j4 * 4] = o;
        }
    }
}

// ---------------- split-K GEMM: kinc = Ek@kin, vinc = Ev@tg ----------------
// M=256(DC), N=128, K=20000. BM=BN=64, BK=32, 25 k-iters per split, 25 splits.
__global__ void __launch_bounds__(256)
splitk_ckv(const float* __restrict__ Ekm, const float* __restrict__ Evm) {
    const int mat = blockIdx.z & 1;
    const int split = blockIdx.z >> 1;
    const float* Am = mat ? Evm : Ekm;
    const float* Xm = mat ? (g_tftg + 128) : g_kin;
    const int ldb = mat ? 256 : 128;
    float* Cm = mat ? g_vinc : g_kinc;

    const int rowBase = blockIdx.y * 64;
    const int colBase = blockIdx.x * 64;
    const int tid = threadIdx.x;
    const int rm = tid >> 4, rn = tid & 15;

    __shared__ float As[32][64];
    __shared__ float Bs[32][64];

    float acc[4][4];
#pragma unroll
    for (int i = 0; i < 4; i++)
#pragma unroll
        for (int j = 0; j < 4; j++) acc[i][j] = 0.0f;

    const int kstart = split * 25 * 32;
    for (int it = 0; it < 25; it++) {
        int kbase = kstart + it * 32;
        __syncthreads();
#pragma unroll
        for (int pp = 0; pp < 2; pp++) {
            int p = tid + pp * 256;
            int row = p >> 3;
            int kq = (p & 7) * 4;
            float4 a4 = *(const float4*)(Am + (size_t)(rowBase + row) * NN + kbase + kq);
            As[kq + 0][row] = a4.x;
            As[kq + 1][row] = a4.y;
            As[kq + 2][row] = a4.z;
            As[kq + 3][row] = a4.w;
            int krow = p >> 4;
            int cq = (p & 15) * 4;
            float4 b4 = *(const float4*)(Xm + (size_t)(kbase + krow) * ldb + colBase + cq);
            *(float4*)&Bs[krow][cq] = b4;
        }
        __syncthreads();
#pragma unroll
        for (int k = 0; k < 32; k++) {
            float4 a4 = *(float4*)&As[k][rm * 4];
            float4 b4 = *(float4*)&Bs[k][rn * 4];
            float av[4] = {a4.x, a4.y, a4.z, a4.w};
            float bv[4] = {b4.x, b4.y, b4.z, b4.w};
#pragma unroll
            for (int i = 0; i < 4; i++)
#pragma unroll
                for (int j = 0; j < 4; j++) acc[i][j] += av[i] * bv[j];
        }
    }
#pragma unroll
    for (int i = 0; i < 4; i++)
#pragma unroll
        for (int j = 0; j < 4; j++)
            atomicAdd(&Cm[(size_t)(rowBase + rm * 4 + i) * 128 + colBase + rn * 4 + j],
                      acc[i][j]);
}

// ---------------- fused attention (plain softmax; scores are O(1)) --------
__global__ void __launch_bounds__(128)
attn_kernel(const int* __restrict__ positions) {
    __shared__ float4 kcs[DC][4];
    __shared__ float4 vcs[DC][4];
    const int h = blockIdx.y;
    const int tid = threadIdx.x;
    for (int p = tid; p < DC * 4; p += 128) {
        int c = p >> 2, d = p & 3;
        kcs[c][d] = *(const float4*)(g_kc + c * 128 + h * 16 + d * 4);
        vcs[c][d] = *(const float4*)(g_vc + c * 128 + h * 16 + d * 4);
    }
    __syncthreads();
    int n = blockIdx.x * 128 + tid;
    if (n >= NN) return;

    const int pos = positions[n];
    const float* qp = g_q + (size_t)n * 128 + h * 16;
    const float* pp = g_peq + (size_t)pos * 128 + h * 16;
    float4 q0 = *(const float4*)(qp + 0);
    float4 q1 = *(const float4*)(qp + 4);
    float4 q2 = *(const float4*)(qp + 8);
    float4 q3 = *(const float4*)(qp + 12);
    float4 p0 = *(const float4*)(pp + 0);
    float4 p1 = *(const float4*)(pp + 4);
    float4 p2 = *(const float4*)(pp + 8);
    float4 p3 = *(const float4*)(pp + 12);
    q0.x += p0.x; q0.y += p0.y; q0.z += p0.z; q0.w += p0.w;
    q1.x += p1.x; q1.y += p1.y; q1.z += p1.z; q1.w += p1.w;
    q2.x += p2.x; q2.y += p2.y; q2.z += p2.z; q2.w += p2.w;
    q3.x += p3.x; q3.y += p3.y; q3.z += p3.z; q3.w += p3.w;

    float s = 0.0f;
    float4 o0 = {0, 0, 0, 0}, o1 = {0, 0, 0, 0}, o2 = {0, 0, 0, 0}, o3 = {0, 0, 0, 0};

    for (int c = 0; c < DC; c++) {
        float4 k0 = kcs[c][0], k1 = kcs[c][1], k2 = kcs[c][2], k3 = kcs[c][3];
        float dot = q0.x * k0.x + q0.y * k0.y + q0.z * k0.z + q0.w * k0.w
                  + q1.x * k1.x + q1.y * k1.y + q1.z * k1.z + q1.w * k1.w
                  + q2.x * k2.x + q2.y * k2.y + q2.z * k2.z + q2.w * k2.w
                  + q3.x * k3.x + q3.y * k3.y + q3.z * k3.z + q3.w * k3.w;
        float p = __expf(dot * 0.25f);
        s += p;
        float4 v0 = vcs[c][0], v1 = vcs[c][1], v2 = vcs[c][2], v3 = vcs[c][3];
        o0.x += p * v0.x; o0.y += p * v0.y; o0.z += p * v0.z; o0.w += p * v0.w;
        o1.x += p * v1.x; o1.y += p * v1.y; o1.z += p * v1.z; o1.w += p * v1.w;
        o2.x += p * v2.x; o2.y += p * v2.y; o2.z += p * v2.z; o2.w += p * v2.w;
        o3.x += p * v3.x; o3.y += p * v3.y; o3.z += p * v3.z; o3.w += p * v3.w;
    }
    float inv = 1.0f / s;
    float* op = g_att + (size_t)n * 128 + h * 16;
    o0.x *= inv; o0.y *= inv; o0.z *= inv; o0.w *= inv;
    o1.x *= inv; o1.y *= inv; o1.z *= inv; o1.w *= inv;
    o2.x *= inv; o2.y *= inv; o2.z *= inv; o2.w *= inv;
    o3.x *= inv; o3.y *= inv; o3.z *= inv; o3.w *= inv;
    *(float4*)(op + 0) = o0;
    *(float4*)(op + 4) = o1;
    *(float4*)(op + 8) = o2;
    *(float4*)(op + 12) = o3;
}

// ---------------- row norms of tfa / tga ----------------
__global__ void norms_kernel() {
    int n = blockIdx.x * blockDim.x + threadIdx.x;
    if (n >= NN) return;
    const float4* a = (const float4*)(g_ab + (size_t)n * 128);
    float sa = 0.0f, sb = 0.0f;
#pragma unroll
    for (int i = 0; i < 16; i++) {
        float4 v = a[i];
        sa += v.x * v.x + v.y * v.y + v.z * v.z + v.w * v.w;
    }
#pragma unroll
    for (int i = 16; i < 32; i++) {
        float4 v = a[i];
        sb += v.x * v.x + v.y * v.y + v.z * v.z + v.w * v.w;
    }
    g_na[n] = sqrtf(sa);
    g_nb[n] = sqrtf(sb);
}

// ---------------- final cosine for 200K pairs ----------------
__global__ void final_pairs(const int* __restrict__ ts, float* __restrict__ out) {
    int t = blockIdx.x * blockDim.x + threadIdx.x;
    if (t >= NT) return;
    int i = ts[2 * t];
    int j = ts[2 * t + 1];
    const float4* a = (const float4*)(g_ab + (size_t)i * 128);
    const float4* b = (const float4*)(g_ab + (size_t)j * 128 + 64);
    float dot = 0.0f;
#pragma unroll
    for (int p = 0; p < 16; p++) {
        float4 av = a[p];
        float4 bv = b[p];
        dot += av.x * bv.x + av.y * bv.y + av.z * bv.z + av.w * bv.w;
    }
    out[t] = dot / fmaxf(g_na[i] * g_nb[j], 1e-8f);
}

// ---------------- host launcher ----------------
static float* symaddr(const void* sym) {
    void* p = nullptr;
    cudaGetSymbolAddress(&p, sym);
    return (float*)p;
}

extern "C" void kernel_launch(void* const* d_in, const int* in_sizes, int n_in,
                              void* d_out, int out_size) {
    const int*   train_sample = (const int*)d_in[1];
    const float* data_feature = (const float*)d_in[2];
    const int*   adj          = (const int*)d_in[3];
    const int*   positions    = (const int*)d_in[4];
    const float* gcn_W   = (const float*)d_in[5];
    const float* gcn_b   = (const float*)d_in[6];
    const float* gcnA2_W = (const float*)d_in[7];
    const float* gcnA2_b = (const float*)d_in[8];
    const float* lin_W   = (const float*)d_in[9];
    const float* lin_b   = (const float*)d_in[10];
    const float* tf_W    = (const float*)d_in[11];
    const float* tf_b    = (const float*)d_in[12];
    const float* tg_W    = (const float*)d_in[13];
    const float* tg_b    = (const float*)d_in[14];
    const float* Wq = (const float*)d_in[15];
    const float* bq = (const float*)d_in[16];
    const float* Wk = (const float*)d_in[17];
    const float* bk = (const float*)d_in[18];
    const float* Wv = (const float*)d_in[19];
    const float* bv = (const float*)d_in[20];
    const float* Wo = (const float*)d_in[21];
    const float* bo = (const float*)d_in[22];
    const float* Ek = (const float*)d_in[23];
    const float* Ev = (const float*)d_in[24];
    const float* pos_emb = (const float*)d_in[25];
    const float* tfa_W = (const float*)d_in[26];
    const float* tfa_b = (const float*)d_in[27];
    const float* tga_W = (const float*)d_in[28];
    const float* tga_b = (const float*)d_in[29];

    float* d_W12   = symaddr(g_W12);
    float* d_b12   = symaddr(g_b12);
    float* d_Wtftg = symaddr(g_Wtftg);
    float* d_btftg = symaddr(g_btftg);
    float* d_Wab   = symaddr(g_Wab);
    float* d_bab   = symaddr(g_bab);
    float* d_h    = symaddr(g_h);
    float* d_g1   = symaddr(g_g1);
    float* d_xa   = symaddr(g_xa);
    float* d_xg   = symaddr(g_xg);
    float* d_tftg = symaddr(g_tftg);
    float* d_q    = symaddr(g_q);
    float* d_peq  = symaddr(g_peq);
    float* d_kinc = symaddr(g_kinc);
    float* d_vinc = symaddr(g_vinc);
    float* d_rsk  = symaddr(g_rsk);
    float* d_rsv  = symaddr(g_rsv);
    float* d_kc   = symaddr(g_kc);
    float* d_vc   = symaddr(g_vc);
    float* d_att  = symaddr(g_att);
    float* d_xf   = symaddr(g_xf);
    float* d_ab   = symaddr(g_ab);

    // 1. pack fused weight blocks
    pack2<<<(512 * 512 + 255) / 256, 256>>>(d_W12, gcn_W, gcnA2_W, d_b12, gcn_b, gcnA2_b, 512, 256);
    pack2<<<(256 * 256 + 255) / 256, 256>>>(d_Wtftg, tf_W, tg_W, d_btftg, tf_b, tg_b, 256, 128);
    pack2<<<(128 * 128 + 255) / 256, 256>>>(d_Wab, tfa_W, tga_W, d_bab, tfa_b, tga_b, 128, 64);

    // 2. CSR construction + Ek/Ev row sums
    deg_zero<<<(NN + 255) / 256, 256>>>();
    deg_count<<<(EE + 255) / 256, 256>>>(adj);
    scan_offsets<<<1, 1024>>>();
    fill_csr<<<(EE + 255) / 256, 256>>>(adj);
    rowsums<<<(2 * DC * 32 + 255) / 256, 256>>>(Ek, Ev);

    // 3. h = data_feature @ [gcn_W | gcnA2_W]  (20000 x 512 x 512)
    sgemm2<0><<<dim3(4, 157), 256>>>(data_feature, d_W12, nullptr, nullptr, d_h, NN, 512, IND);

    // 4. CSR gather + fused finalize -> g1 (sigmoid), xa
    gcn_gather<<<NN, 128>>>();

    // 5. x_g = leaky(g1 @ lin_W + lin_b); [tf|tg] = leaky(xa @ [tf_W|tg_W] + b)
    sgemm2<1><<<dim3(1, 157), 256>>>(d_g1, lin_W, lin_b, nullptr, d_xg, NN, 128, 256);
    sgemm2<1><<<dim3(2, 157), 256>>>(d_xa, d_Wtftg, d_btftg, nullptr, d_tftg, NN, 256, 256);

    // 6. q = xg@Wq + bq; peq = pos_emb@Wq; kin = tf + pe
    sgemm2<0><<<dim3(1, 157), 256>>>(d_xg, Wq, bq, nullptr, d_q, NN, 128, 128);
    sgemm2<0><<<dim3(1, 4), 256>>>(pos_emb, Wq, nullptr, nullptr, d_peq, 512, 128, 128);
    build_kin<<<(NN * 128 + 255) / 256, 256>>>(positions, pos_emb);

    // 7. kinc = Ek@kin, vinc = Ev@tg (split-K), then project:
    //    kc = kinc@Wk + rowsum(Ek)*bk ; vc = vinc@Wv + rowsum(Ev)*bv
    zero_cc<<<(DC * 128 + 255) / 256, 256>>>();
    splitk_ckv<<<dim3(2, 4, 50), 256>>>(Ek, Ev);
    sgemm2<2><<<dim3(1, 2), 256>>>(d_kinc, Wk, bk, d_rsk, d_kc, DC, 128, 128);
    sgemm2<2><<<dim3(1, 2), 256>>>(d_vinc, Wv, bv, d_rsv, d_vc, DC, 128, 128);

    // 8. fused attention
    attn_kernel<<<dim3(157, HEADS), 128>>>(positions);

    // 9. x_f = att @ Wo + bo; [tfa|tga] = leaky(x_f @ [tfa_W|tga_W] + b)
    sgemm2<0><<<dim3(1, 157), 256>>>(d_att, Wo, bo, nullptr, d_xf, NN, 128, 128);
    sgemm2<1><<<dim3(1, 157), 256>>>(d_xf, d_Wab, d_bab, nullptr, d_ab, NN, 128, 128);

    // 10. norms + final cosine pairs
    norms_kernel<<<(NN + 255) / 256, 256>>>();
    final_pairs<<<(NT + 255) / 256, 256>>>(train_sample, (float*)d_out);
}

// round 9
// speedup vs baseline: 1.1245x; 1.1245x over previous
#include <cuda_runtime.h>
#include <math.h>

// ---------------- problem constants ----------------
constexpr int NN   = 20000;
constexpr int EE   = 320000;
constexpr int NT   = 200000;
constexpr int IND  = 512;   // INPUT_DIM
constexpr int DC   = 256;
constexpr int HEADS = 8;

// ---------------- scratch (static device globals; no runtime alloc) --------
__device__ float g_W12[512 * 512];
__device__ float g_b12[512];
__device__ float g_Wtftg[256 * 256];
__device__ float g_btftg[256];
__device__ float g_Wab[128 * 128];
__device__ float g_bab[128];

__device__ float g_h[(size_t)NN * 512];    // [h_gcn1 | h_gcn2]
__device__ float g_dinv[NN];

// CSR structures for the edge gather
__device__ int g_deg[NN];
__device__ int g_cnt[NN];
__device__ int g_off[NN + 1];
__device__ int g_esrc[EE];

__device__ float g_g1[(size_t)NN * 256];   // sigmoid(gcn1)
__device__ float g_xa[(size_t)NN * 256];   // gcn2 raw
__device__ float g_xg[(size_t)NN * 128];
__device__ float g_tftg[(size_t)NN * 256]; // [tf | tg]

__device__ float g_kin[(size_t)NN * 128];  // tf + pos_emb lookup
__device__ float g_q[(size_t)NN * 128];    // xg @ Wq + bq (pos term added in attn)
__device__ float g_peq[512 * 128];         // pos_emb @ Wq

__device__ float g_kinc[DC * 128];         // Ek @ kin
__device__ float g_vinc[DC * 128];         // Ev @ tg
__device__ float g_rsk[DC];                // rowsum(Ek)
__device__ float g_rsv[DC];                // rowsum(Ev)
__device__ float g_kc[DC * 128];
__device__ float g_vc[DC * 128];

__device__ float g_att[(size_t)NN * 128];
__device__ float g_xf[(size_t)NN * 128];
__device__ float g_ab[(size_t)NN * 128];   // [tfa | tga], leaky applied
__device__ float g_na[NN];
__device__ float g_nb[NN];

// ---------------- small helpers ----------------
__global__ void zero_cc() {
    int i = blockIdx.x * blockDim.x + threadIdx.x;
    if (i < DC * 128) { g_kinc[i] = 0.0f; g_vinc[i] = 0.0f; }
}

// pack W = [W1 | W2] (rows x 2*hc), b = [b1 | b2]
__global__ void pack2(float* __restrict__ W, const float* __restrict__ W1,
                      const float* __restrict__ W2, float* __restrict__ b,
                      const float* __restrict__ b1, const float* __restrict__ b2,
                      int rows, int hc) {
    int idx = blockIdx.x * blockDim.x + threadIdx.x;
    int tot = rows * 2 * hc;
    if (idx < tot) {
        int r = idx / (2 * hc);
        int c = idx - r * 2 * hc;
        W[idx] = (c < hc) ? W1[r * hc + c] : W2[r * hc + (c - hc)];
    }
    if (idx < 2 * hc) b[idx] = (idx < hc) ? b1[idx] : b2[idx - hc];
}

// ---------------- CSR construction ----------------
__global__ void deg_zero() {
    int i = blockIdx.x * blockDim.x + threadIdx.x;
    if (i < NN) { g_deg[i] = 0; g_cnt[i] = 0; }
}
__global__ void deg_count(const int* __restrict__ adj) {
    int e = blockIdx.x * blockDim.x + threadIdx.x;
    if (e < EE) atomicAdd(&g_deg[adj[EE + e]], 1);
}
__global__ void __launch_bounds__(1024) scan_offsets() {
    __shared__ int partial[1024];
    const int tid = threadIdx.x;
    const int PER = (NN + 1023) / 1024;   // 20
    const int base = tid * PER;
    int s = 0;
#pragma unroll
    for (int i = 0; i < PER; i++) {
        int idx = base + i;
        if (idx < NN) s += g_deg[idx];
    }
    partial[tid] = s;
    __syncthreads();
    for (int off = 1; off < 1024; off <<= 1) {
        int v = 0;
        if (tid >= off) v = partial[tid - off];
        __syncthreads();
        if (tid >= off) partial[tid] += v;
        __syncthreads();
    }
    int run = (tid > 0) ? partial[tid - 1] : 0;
#pragma unroll
    for (int i = 0; i < PER; i++) {
        int idx = base + i;
        if (idx < NN) {
            g_off[idx] = run;
            int d = g_deg[idx];
            run += d;
            g_dinv[idx] = rsqrtf(1.0f + (float)d);
        }
    }
    if (tid == 0) g_off[NN] = EE;
}
__global__ void fill_csr(const int* __restrict__ adj) {
    int e = blockIdx.x * blockDim.x + threadIdx.x;
    if (e >= EE) return;
    int s = adj[e];
    int d = adj[EE + e];
    int pos = g_off[d] + atomicAdd(&g_cnt[d], 1);
    g_esrc[pos] = s;
}

// ---------------- row sums of Ek / Ev (for bias folding) -------------------
__global__ void rowsums(const float* __restrict__ Ek, const float* __restrict__ Ev) {
    int gw = (blockIdx.x * blockDim.x + threadIdx.x) >> 5;
    int lane = threadIdx.x & 31;
    if (gw >= 2 * DC) return;
    const float* src = (gw < DC) ? Ek + (size_t)gw * NN : Ev + (size_t)(gw - DC) * NN;
    float s = 0.0f;
    for (int i = lane * 4; i < NN; i += 128) {
        float4 v = *(const float4*)(src + i);
        s += v.x + v.y + v.z + v.w;
    }
#pragma unroll
    for (int o = 16; o > 0; o >>= 1) s += __shfl_xor_sync(0xffffffffu, s, o);
    if (lane == 0) {
        if (gw < DC) g_rsk[gw] = s;
        else         g_rsv[gw - DC] = s;
    }
}

// ---------------- CSR gather + fused GCN finalize --------------------------
__global__ void __launch_bounds__(128) gcn_gather() {
    __shared__ int   s_src[128];
    __shared__ float s_coef[128];
    const int d = blockIdx.x;
    const int tid = threadIdx.x;
    const int beg = g_off[d];
    const int deg = g_off[d + 1] - beg;
    const float di = g_dinv[d];

    float4 acc = {0.f, 0.f, 0.f, 0.f};
    for (int c0 = 0; c0 < deg; c0 += 128) {
        int m = min(128, deg - c0);
        if (tid < m) {
            int s = g_esrc[beg + c0 + tid];
            s_src[tid] = s;
            s_coef[tid] = g_dinv[s] * di;
        }
        __syncthreads();
        int i = 0;
#pragma unroll 1
        for (; i + 4 <= m; i += 4) {
            const float4 h0 = *(const float4*)(g_h + (size_t)s_src[i + 0] * 512 + tid * 4);
            const float4 h1 = *(const float4*)(g_h + (size_t)s_src[i + 1] * 512 + tid * 4);
            const float4 h2 = *(const float4*)(g_h + (size_t)s_src[i + 2] * 512 + tid * 4);
            const float4 h3 = *(const float4*)(g_h + (size_t)s_src[i + 3] * 512 + tid * 4);
            float c0f = s_coef[i + 0], c1f = s_coef[i + 1];
            float c2f = s_coef[i + 2], c3f = s_coef[i + 3];
            acc.x += h0.x * c0f; acc.y += h0.y * c0f; acc.z += h0.z * c0f; acc.w += h0.w * c0f;
            acc.x += h1.x * c1f; acc.y += h1.y * c1f; acc.z += h1.z * c1f; acc.w += h1.w * c1f;
            acc.x += h2.x * c2f; acc.y += h2.y * c2f; acc.z += h2.z * c2f; acc.w += h2.w * c2f;
            acc.x += h3.x * c3f; acc.y += h3.y * c3f; acc.z += h3.z * c3f; acc.w += h3.w * c3f;
        }
        for (; i < m; i++) {
            const float4 hv = *(const float4*)(g_h + (size_t)s_src[i] * 512 + tid * 4);
            float cf = s_coef[i];
            acc.x += hv.x * cf; acc.y += hv.y * cf; acc.z += hv.z * cf; acc.w += hv.w * cf;
        }
        __syncthreads();
    }

    const int j = tid * 4;
    const float4 hd = *(const float4*)(g_h + (size_t)d * 512 + j);
    const float4 bb = *(const float4*)(g_b12 + j);
    const float d2 = di * di;
    float4 v;
    v.x = acc.x + hd.x * d2 + bb.x;
    v.y = acc.y + hd.y * d2 + bb.y;
    v.z = acc.z + hd.z * d2 + bb.z;
    v.w = acc.w + hd.w * d2 + bb.w;
    if (j < 256) {
        float4 o;
        o.x = 1.0f / (1.0f + __expf(-v.x));
        o.y = 1.0f / (1.0f + __expf(-v.y));
        o.z = 1.0f / (1.0f + __expf(-v.z));
        o.w = 1.0f / (1.0f + __expf(-v.w));
        *(float4*)(g_g1 + (size_t)d * 256 + j) = o;
    } else {
        *(float4*)(g_xa + (size_t)d * 256 + (j - 256)) = v;
    }
}

// ---------------- kin = tf + pos_emb[positions] ----------------------------
__global__ void build_kin(const int* __restrict__ positions,
                          const float* __restrict__ pos_emb) {
    int idx = blockIdx.x * blockDim.x + threadIdx.x;
    if (idx >= NN * 128) return;
    int n = idx >> 7;
    int j = idx & 127;
    g_kin[idx] = g_tftg[(size_t)n * 256 + j] + pos_emb[positions[n] * 128 + j];
}

// ---------------- SGEMM: C = act(A@B + bias) -------------------------------
// BM=BN=128, BK=16, double-buffered smem, 256 threads, 8x8 per thread.
// ACT: 0 = none, 1 = leaky relu, 2 = C = A@B + rowscale[row]*bias[col]
template <int ACT>
__global__ void __launch_bounds__(256)
sgemm2(const float* __restrict__ A, const float* __restrict__ B,
       const float* __restrict__ bias, const float* __restrict__ rowscale,
       float* __restrict__ C, int M, int N, int K) {
    __shared__ float As[2][16][128];
    __shared__ float Bs[2][16][128];
    const int tid = threadIdx.x;
    const int rowBase = blockIdx.y * 128;
    const int colBase = blockIdx.x * 128;

    const int lr = tid >> 1;           // 0..127 A row
    const int lq = (tid & 1) * 8;      // 0 or 8 k-offset
    const int br = tid >> 5;           // 0..7 B k-row (and br+8)
    const int bc = (tid & 31) * 4;     // B col
    const int rm = tid >> 4;           // 0..15
    const int rn = tid & 15;           // 0..15

    const int arow = rowBase + lr;
    const bool aval = arow < M;
    const float* Aptr = A + (size_t)arow * K + lq;
    const float* Bptr = B + colBase + bc;

    float acc[8][8];
#pragma unroll
    for (int i = 0; i < 8; i++)
#pragma unroll
        for (int j = 0; j < 8; j++) acc[i][j] = 0.0f;

    const int niter = K >> 4;
    float4 a0, a1, b0, b1;
    // preload iter 0
    a0 = aval ? *(const float4*)(Aptr + 0) : make_float4(0, 0, 0, 0);
    a1 = aval ? *(const float4*)(Aptr + 4) : make_float4(0, 0, 0, 0);
    b0 = *(const float4*)(Bptr + (size_t)br * N);
    b1 = *(const float4*)(Bptr + (size_t)(br + 8) * N);
    As[0][lq + 0][lr] = a0.x; As[0][lq + 1][lr] = a0.y;
    As[0][lq + 2][lr] = a0.z; As[0][lq + 3][lr] = a0.w;
    As[0][lq + 4][lr] = a1.x; As[0][lq + 5][lr] = a1.y;
    As[0][lq + 6][lr] = a1.z; As[0][lq + 7][lr] = a1.w;
    *(float4*)&Bs[0][br][bc] = b0;
    *(float4*)&Bs[0][br + 8][bc] = b1;
    __syncthreads();

    for (int it = 0; it < niter; it++) {
        const int cur = it & 1;
        if (it + 1 < niter) {
            const int k0 = (it + 1) << 4;
            a0 = aval ? *(const float4*)(Aptr + k0) : make_float4(0, 0, 0, 0);
            a1 = aval ? *(const float4*)(Aptr + k0 + 4) : make_float4(0, 0, 0, 0);
            b0 = *(const float4*)(Bptr + (size_t)(k0 + br) * N);
            b1 = *(const float4*)(Bptr + (size_t)(k0 + br + 8) * N);
        }
#pragma unroll
        for (int k = 0; k < 16; k++) {
            float4 av0 = *(const float4*)&As[cur][k][rm * 8];
            float4 av1 = *(const float4*)&As[cur][k][rm * 8 + 4];
            float4 bv0 = *(const float4*)&Bs[cur][k][rn * 8];
            float4 bv1 = *(const float4*)&Bs[cur][k][rn * 8 + 4];
            float av[8] = {av0.x, av0.y, av0.z, av0.w, av1.x, av1.y, av1.z, av1.w};
            float bv[8] = {bv0.x, bv0.y, bv0.z, bv0.w, bv1.x, bv1.y, bv1.z, bv1.w};
#pragma unroll
            for (int i = 0; i < 8; i++)
#pragma unroll
                for (int j = 0; j < 8; j++) acc[i][j] += av[i] * bv[j];
        }
        if (it + 1 < niter) {
            const int nxt = cur ^ 1;
            As[nxt][lq + 0][lr] = a0.x; As[nxt][lq + 1][lr] = a0.y;
            As[nxt][lq + 2][lr] = a0.z; As[nxt][lq + 3][lr] = a0.w;
            As[nxt][lq + 4][lr] = a1.x; As[nxt][lq + 5][lr] = a1.y;
            As[nxt][lq + 6][lr] = a1.z; As[nxt][lq + 7][lr] = a1.w;
            *(float4*)&Bs[nxt][br][bc] = b0;
            *(float4*)&Bs[nxt][br + 8][bc] = b1;
        }
        __syncthreads();
    }

#pragma unroll
    for (int i = 0; i < 8; i++) {
        int row = rowBase + rm * 8 + i;
        if (row >= M) continue;
        float rsc = (ACT == 2) ? rowscale[row] : 1.0f;
        int col0 = colBase + rn * 8;
#pragma unroll
        for (int j4 = 0; j4 < 2; j4++) {
            float4 o;
            float* op = &o.x;
#pragma unroll
            for (int j = 0; j < 4; j++) {
                int jj = j4 * 4 + j;
                float v = acc[i][jj];
                if (bias) v += rsc * bias[col0 + jj];
                if (ACT == 1) v = (v >= 0.0f) ? v : 0.01f * v;
                op[j] = v;
            }
            *(float4*)&C[(size_t)row * N + col0 + j4 * 4] = o;
        }
    }
}

// ---------------- split-K GEMM: kinc = Ek@kin, vinc = Ev@tg ----------------
// M=256(DC), N=128, K=20000. BM=BN=64, BK=32, 25 k-iters per split, 25 splits.
__global__ void __launch_bounds__(256)
splitk_ckv(const float* __restrict__ Ekm, const float* __restrict__ Evm) {
    const int mat = blockIdx.z & 1;
    const int split = blockIdx.z >> 1;
    const float* Am = mat ? Evm : Ekm;
    const float* Xm = mat ? (g_tftg + 128) : g_kin;
    const int ldb = mat ? 256 : 128;
    float* Cm = mat ? g_vinc : g_kinc;

    const int rowBase = blockIdx.y * 64;
    const int colBase = blockIdx.x * 64;
    const int tid = threadIdx.x;
    const int rm = tid >> 4, rn = tid & 15;

    __shared__ float As[32][64];
    __shared__ float Bs[32][64];

    float acc[4][4];
#pragma unroll
    for (int i = 0; i < 4; i++)
#pragma unroll
        for (int j = 0; j < 4; j++) acc[i][j] = 0.0f;

    const int kstart = split * 25 * 32;
    for (int it = 0; it < 25; it++) {
        int kbase = kstart + it * 32;
        __syncthreads();
#pragma unroll
        for (int pp = 0; pp < 2; pp++) {
            int p = tid + pp * 256;
            int row = p >> 3;
            int kq = (p & 7) * 4;
            float4 a4 = *(const float4*)(Am + (size_t)(rowBase + row) * NN + kbase + kq);
            As[kq + 0][row] = a4.x;
            As[kq + 1][row] = a4.y;
            As[kq + 2][row] = a4.z;
            As[kq + 3][row] = a4.w;
            int krow = p >> 4;
            int cq = (p & 15) * 4;
            float4 b4 = *(const float4*)(Xm + (size_t)(kbase + krow) * ldb + colBase + cq);
            *(float4*)&Bs[krow][cq] = b4;
        }
        __syncthreads();
#pragma unroll
        for (int k = 0; k < 32; k++) {
            float4 a4 = *(float4*)&As[k][rm * 4];
            float4 b4 = *(float4*)&Bs[k][rn * 4];
            float av[4] = {a4.x, a4.y, a4.z, a4.w};
            float bv[4] = {b4.x, b4.y, b4.z, b4.w};
#pragma unroll
            for (int i = 0; i < 4; i++)
#pragma unroll
                for (int j = 0; j < 4; j++) acc[i][j] += av[i] * bv[j];
        }
    }
#pragma unroll
    for (int i = 0; i < 4; i++)
#pragma unroll
        for (int j = 0; j < 4; j++)
            atomicAdd(&Cm[(size_t)(rowBase + rm * 4 + i) * 128 + colBase + rn * 4 + j],
                      acc[i][j]);
}

// ---------------- fused attention (plain softmax; scores are O(1)) --------
__global__ void __launch_bounds__(128)
attn_kernel(const int* __restrict__ positions) {
    __shared__ float4 kcs[DC][4];
    __shared__ float4 vcs[DC][4];
    const int h = blockIdx.y;
    const int tid = threadIdx.x;
    for (int p = tid; p < DC * 4; p += 128) {
        int c = p >> 2, d = p & 3;
        kcs[c][d] = *(const float4*)(g_kc + c * 128 + h * 16 + d * 4);
        vcs[c][d] = *(const float4*)(g_vc + c * 128 + h * 16 + d * 4);
    }
    __syncthreads();
    int n = blockIdx.x * 128 + tid;
    if (n >= NN) return;

    const int pos = positions[n];
    const float* qp = g_q + (size_t)n * 128 + h * 16;
    const float* pp = g_peq + (size_t)pos * 128 + h * 16;
    float4 q0 = *(const float4*)(qp + 0);
    float4 q1 = *(const float4*)(qp + 4);
    float4 q2 = *(const float4*)(qp + 8);
    float4 q3 = *(const float4*)(qp + 12);
    float4 p0 = *(const float4*)(pp + 0);
    float4 p1 = *(const float4*)(pp + 4);
    float4 p2 = *(const float4*)(pp + 8);
    float4 p3 = *(const float4*)(pp + 12);
    q0.x += p0.x; q0.y += p0.y; q0.z += p0.z; q0.w += p0.w;
    q1.x += p1.x; q1.y += p1.y; q1.z += p1.z; q1.w += p1.w;
    q2.x += p2.x; q2.y += p2.y; q2.z += p2.z; q2.w += p2.w;
    q3.x += p3.x; q3.y += p3.y; q3.z += p3.z; q3.w += p3.w;

    float s = 0.0f;
    float4 o0 = {0, 0, 0, 0}, o1 = {0, 0, 0, 0}, o2 = {0, 0, 0, 0}, o3 = {0, 0, 0, 0};

    for (int c = 0; c < DC; c++) {
        float4 k0 = kcs[c][0], k1 = kcs[c][1], k2 = kcs[c][2], k3 = kcs[c][3];
        float dot = q0.x * k0.x + q0.y * k0.y + q0.z * k0.z + q0.w * k0.w
                  + q1.x * k1.x + q1.y * k1.y + q1.z * k1.z + q1.w * k1.w
                  + q2.x * k2.x + q2.y * k2.y + q2.z * k2.z + q2.w * k2.w
                  + q3.x * k3.x + q3.y * k3.y + q3.z * k3.z + q3.w * k3.w;
        float p = __expf(dot * 0.25f);
        s += p;
        float4 v0 = vcs[c][0], v1 = vcs[c][1], v2 = vcs[c][2], v3 = vcs[c][3];
        o0.x += p * v0.x; o0.y += p * v0.y; o0.z += p * v0.z; o0.w += p * v0.w;
        o1.x += p * v1.x; o1.y += p * v1.y; o1.z += p * v1.z; o1.w += p * v1.w;
        o2.x += p * v2.x; o2.y += p * v2.y; o2.z += p * v2.z; o2.w += p * v2.w;
        o3.x += p * v3.x; o3.y += p * v3.y; o3.z += p * v3.z; o3.w += p * v3.w;
    }
    float inv = 1.0f / s;
    float* op = g_att + (size_t)n * 128 + h * 16;
    o0.x *= inv; o0.y *= inv; o0.z *= inv; o0.w *= inv;
    o1.x *= inv; o1.y *= inv; o1.z *= inv; o1.w *= inv;
    o2.x *= inv; o2.y *= inv; o2.z *= inv; o2.w *= inv;
    o3.x *= inv; o3.y *= inv; o3.z *= inv; o3.w *= inv;
    *(float4*)(op + 0) = o0;
    *(float4*)(op + 4) = o1;
    *(float4*)(op + 8) = o2;
    *(float4*)(op + 12) = o3;
}

// ---------------- row norms of tfa / tga ----------------
__global__ void norms_kernel() {
    int n = blockIdx.x * blockDim.x + threadIdx.x;
    if (n >= NN) return;
    const float4* a = (const float4*)(g_ab + (size_t)n * 128);
    float sa = 0.0f, sb = 0.0f;
#pragma unroll
    for (int i = 0; i < 16; i++) {
        float4 v = a[i];
        sa += v.x * v.x + v.y * v.y + v.z * v.z + v.w * v.w;
    }
#pragma unroll
    for (int i = 16; i < 32; i++) {
        float4 v = a[i];
        sb += v.x * v.x + v.y * v.y + v.z * v.z + v.w * v.w;
    }
    g_na[n] = sqrtf(sa);
    g_nb[n] = sqrtf(sb);
}

// ---------------- final cosine for 200K pairs ----------------
__global__ void final_pairs(const int* __restrict__ ts, float* __restrict__ out) {
    int t = blockIdx.x * blockDim.x + threadIdx.x;
    if (t >= NT) return;
    int i = ts[2 * t];
    int j = ts[2 * t + 1];
    const float4* a = (const float4*)(g_ab + (size_t)i * 128);
    const float4* b = (const float4*)(g_ab + (size_t)j * 128 + 64);
    float dot = 0.0f;
#pragma unroll
    for (int p = 0; p < 16; p++) {
        float4 av = a[p];
        float4 bv = b[p];
        dot += av.x * bv.x + av.y * bv.y + av.z * bv.z + av.w * bv.w;
    }
    out[t] = dot / fmaxf(g_na[i] * g_nb[j], 1e-8f);
}

// ---------------- host launcher ----------------
static float* symaddr(const void* sym) {
    void* p = nullptr;
    cudaGetSymbolAddress(&p, sym);
    return (float*)p;
}

extern "C" void kernel_launch(void* const* d_in, const int* in_sizes, int n_in,
                              void* d_out, int out_size) {
    const int*   train_sample = (const int*)d_in[1];
    const float* data_feature = (const float*)d_in[2];
    const int*   adj          = (const int*)d_in[3];
    const int*   positions    = (const int*)d_in[4];
    const float* gcn_W   = (const float*)d_in[5];
    const float* gcn_b   = (const float*)d_in[6];
    const float* gcnA2_W = (const float*)d_in[7];
    const float* gcnA2_b = (const float*)d_in[8];
    const float* lin_W   = (const float*)d_in[9];
    const float* lin_b   = (const float*)d_in[10];
    const float* tf_W    = (const float*)d_in[11];
    const float* tf_b    = (const float*)d_in[12];
    const float* tg_W    = (const float*)d_in[13];
    const float* tg_b    = (const float*)d_in[14];
    const float* Wq = (const float*)d_in[15];
    const float* bq = (const float*)d_in[16];
    const float* Wk = (const float*)d_in[17];
    const float* bk = (const float*)d_in[18];
    const float* Wv = (const float*)d_in[19];
    const float* bv = (const float*)d_in[20];
    const float* Wo = (const float*)d_in[21];
    const float* bo = (const float*)d_in[22];
    const float* Ek = (const float*)d_in[23];
    const float* Ev = (const float*)d_in[24];
    const float* pos_emb = (const float*)d_in[25];
    const float* tfa_W = (const float*)d_in[26];
    const float* tfa_b = (const float*)d_in[27];
    const float* tga_W = (const float*)d_in[28];
    const float* tga_b = (const float*)d_in[29];

    float* d_W12   = symaddr(g_W12);
    float* d_b12   = symaddr(g_b12);
    float* d_Wtftg = symaddr(g_Wtftg);
    float* d_btftg = symaddr(g_btftg);
    float* d_Wab   = symaddr(g_Wab);
    float* d_bab   = symaddr(g_bab);
    float* d_h    = symaddr(g_h);
    float* d_g1   = symaddr(g_g1);
    float* d_xa   = symaddr(g_xa);
    float* d_xg   = symaddr(g_xg);
    float* d_tftg = symaddr(g_tftg);
    float* d_q    = symaddr(g_q);
    float* d_peq  = symaddr(g_peq);
    float* d_kinc = symaddr(g_kinc);
    float* d_vinc = symaddr(g_vinc);
    float* d_rsk  = symaddr(g_rsk);
    float* d_rsv  = symaddr(g_rsv);
    float* d_kc   = symaddr(g_kc);
    float* d_vc   = symaddr(g_vc);
    float* d_att  = symaddr(g_att);
    float* d_xf   = symaddr(g_xf);
    float* d_ab   = symaddr(g_ab);

    // 1. pack fused weight blocks
    pack2<<<(512 * 512 + 255) / 256, 256>>>(d_W12, gcn_W, gcnA2_W, d_b12, gcn_b, gcnA2_b, 512, 256);
    pack2<<<(256 * 256 + 255) / 256, 256>>>(d_Wtftg, tf_W, tg_W, d_btftg, tf_b, tg_b, 256, 128);
    pack2<<<(128 * 128 + 255) / 256, 256>>>(d_Wab, tfa_W, tga_W, d_bab, tfa_b, tga_b, 128, 64);

    // 2. CSR construction + Ek/Ev row sums
    deg_zero<<<(NN + 255) / 256, 256>>>();
    deg_count<<<(EE + 255) / 256, 256>>>(adj);
    scan_offsets<<<1, 1024>>>();
    fill_csr<<<(EE + 255) / 256, 256>>>(adj);
    rowsums<<<(2 * DC * 32 + 255) / 256, 256>>>(Ek, Ev);

    // 3. h = data_feature @ [gcn_W | gcnA2_W]  (20000 x 512 x 512)
    sgemm2<0><<<dim3(4, 157), 256>>>(data_feature, d_W12, nullptr, nullptr, d_h, NN, 512, IND);

    // 4. CSR gather + fused finalize -> g1 (sigmoid), xa
    gcn_gather<<<NN, 128>>>();

    // 5. x_g = leaky(g1 @ lin_W + lin_b); [tf|tg] = leaky(xa @ [tf_W|tg_W] + b)
    sgemm2<1><<<dim3(1, 157), 256>>>(d_g1, lin_W, lin_b, nullptr, d_xg, NN, 128, 256);
    sgemm2<1><<<dim3(2, 157), 256>>>(d_xa, d_Wtftg, d_btftg, nullptr, d_tftg, NN, 256, 256);

    // 6. q = xg@Wq + bq; peq = pos_emb@Wq; kin = tf + pe
    sgemm2<0><<<dim3(1, 157), 256>>>(d_xg, Wq, bq, nullptr, d_q, NN, 128, 128);
    sgemm2<0><<<dim3(1, 4), 256>>>(pos_emb, Wq, nullptr, nullptr, d_peq, 512, 128, 128);
    build_kin<<<(NN * 128 + 255) / 256, 256>>>(positions, pos_emb);

    // 7. kinc = Ek@kin, vinc = Ev@tg (split-K), then project:
    //    kc = kinc@Wk + rowsum(Ek)*bk ; vc = vinc@Wv + rowsum(Ev)*bv
    zero_cc<<<(DC * 128 + 255) / 256, 256>>>();
    splitk_ckv<<<dim3(2, 4, 50), 256>>>(Ek, Ev);
    sgemm2<2><<<dim3(1, 2), 256>>>(d_kinc, Wk, bk, d_rsk, d_kc, DC, 128, 128);
    sgemm2<2><<<dim3(1, 2), 256>>>(d_vinc, Wv, bv, d_rsv, d_vc, DC, 128, 128);

    // 8. fused attention
    attn_kernel<<<dim3(157, HEADS), 128>>>(positions);

    // 9. x_f = att @ Wo + bo; [tfa|tga] = leaky(x_f @ [tfa_W|tga_W] + b)
    sgemm2<0><<<dim3(1, 157), 256>>>(d_att, Wo, bo, nullptr, d_xf, NN, 128, 128);
    sgemm2<1><<<dim3(1, 157), 256>>>(d_xf, d_Wab, d_bab, nullptr, d_ab, NN, 128, 128);

    // 10. norms + final cosine pairs
    norms_kernel<<<(NN + 255) / 256, 256>>>();
    final_pairs<<<(NT + 255) / 256, 256>>>(train_sample, (float*)d_out);
}

// round 11
// speedup vs baseline: 1.3785x; 1.2259x over previous
#include <cuda_runtime.h>
#include <math.h>
#include <stdint.h>

// ---------------- problem constants ----------------
constexpr int NN   = 20000;
constexpr int EE   = 320000;
constexpr int NT   = 200000;
constexpr int DC   = 256;
constexpr int HEADS = 8;

// ---------------- scratch (static device globals; no runtime alloc) --------
__device__ float g_W12t[512 * 512];        // transposed fused weights [n][k]
__device__ float g_b12[512];
__device__ float g_Wtftg[256 * 256];
__device__ float g_btftg[256];
__device__ float g_Wab[128 * 128];
__device__ float g_bab[128];

__device__ float g_h[(size_t)NN * 512];    // [h_gcn1 | h_gcn2]
__device__ float g_dinv[NN];

__device__ int g_deg[NN];
__device__ int g_cnt[NN];
__device__ int g_off[NN + 1];
__device__ int g_esrc[EE];

__device__ float g_g1[(size_t)NN * 256];
__device__ float g_xa[(size_t)NN * 256];
__device__ float g_xg[(size_t)NN * 128];
__device__ float g_tftg[(size_t)NN * 256];

__device__ float g_kin[(size_t)NN * 128];
__device__ float g_q[(size_t)NN * 128];
__device__ float g_peq[512 * 128];

__device__ float g_kinc[DC * 128];
__device__ float g_vinc[DC * 128];
__device__ float g_rsk[DC];
__device__ float g_rsv[DC];
__device__ float g_kc[DC * 128];
__device__ float g_vc[DC * 128];

__device__ float g_att[(size_t)NN * 128];
__device__ float g_xf[(size_t)NN * 128];
__device__ float g_ab[(size_t)NN * 128];
__device__ float g_na[NN];
__device__ float g_nb[NN];

// ---------------- tf32 helpers ----------------
__device__ __forceinline__ uint32_t cvt_tf32(float f) {
    uint32_t u;
    asm("cvt.rna.tf32.f32 %0, %1;" : "=r"(u) : "f"(f));
    return u;
}
__device__ __forceinline__ uint4 cvt_tf32x4(float4 v) {
    uint4 r;
    r.x = cvt_tf32(v.x); r.y = cvt_tf32(v.y);
    r.z = cvt_tf32(v.z); r.w = cvt_tf32(v.w);
    return r;
}
#define MMA_TF32(c, a, b) \
    asm volatile( \
        "mma.sync.aligned.m16n8k8.row.col.f32.tf32.tf32.f32 " \
        "{%0,%1,%2,%3}, {%4,%5,%6,%7}, {%8,%9}, {%0,%1,%2,%3};" \
        : "+f"((c)[0]), "+f"((c)[1]), "+f"((c)[2]), "+f"((c)[3]) \
        : "r"((a)[0]), "r"((a)[1]), "r"((a)[2]), "r"((a)[3]), \
          "r"((b)[0]), "r"((b)[1]))

// ---------------- tf32 mma.sync GEMM: h = data_feature @ W12 ---------------
// BM=128, BN=128, BK=32. 256 threads = 8 warps; warp tile 64x32 (4x4 m16n8k8).
// A: [NN][512] row-major. B: g_W12t [n][k] (col-major k8xn8 fragments).
constexpr int SPAD = 36;  // smem row stride in words (conflict-free frags)
__global__ void __launch_bounds__(256) mma_h(const float* __restrict__ A) {
    __shared__ uint32_t sA[128 * SPAD];
    __shared__ uint32_t sB[128 * SPAD];
    const int tid = threadIdx.x;
    const int lane = tid & 31, wid = tid >> 5;
    const int wr = wid >> 2, wc = wid & 3;       // warp row (0..1) / col (0..3)
    const int gq = lane >> 2, tq = lane & 3;     // group / thread-in-group
    const int rowBase = blockIdx.y * 128;
    const int colBase = blockIdx.x * 128;

    float c[4][4][4];
#pragma unroll
    for (int mt = 0; mt < 4; mt++)
#pragma unroll
        for (int nt = 0; nt < 4; nt++)
#pragma unroll
            for (int r = 0; r < 4; r++) c[mt][nt][r] = 0.0f;

    // per-thread gmem->smem chunks: idx = tid + p*256; row = idx>>3, c4 = idx&7
    int lrow[4], lc4[4];
#pragma unroll
    for (int p = 0; p < 4; p++) {
        int idx = tid + p * 256;
        lrow[p] = idx >> 3;
        lc4[p] = idx & 7;
    }

    uint4 ra[4], rb[4];
    // preload iter 0
#pragma unroll
    for (int p = 0; p < 4; p++) {
        int arow = rowBase + lrow[p];
        float4 av = (arow < NN)
            ? *(const float4*)(A + (size_t)arow * 512 + lc4[p] * 4)
            : make_float4(0.f, 0.f, 0.f, 0.f);
        ra[p] = cvt_tf32x4(av);
        float4 bv = *(const float4*)(g_W12t + (size_t)(colBase + lrow[p]) * 512 + lc4[p] * 4);
        rb[p] = cvt_tf32x4(bv);
    }
#pragma unroll
    for (int p = 0; p < 4; p++) {
        *(uint4*)&sA[lrow[p] * SPAD + lc4[p] * 4] = ra[p];
        *(uint4*)&sB[lrow[p] * SPAD + lc4[p] * 4] = rb[p];
    }
    __syncthreads();

    for (int it = 0; it < 16; it++) {
        if (it + 1 < 16) {
            const int k0 = (it + 1) * 32;
#pragma unroll
            for (int p = 0; p < 4; p++) {
                int arow = rowBase + lrow[p];
                float4 av = (arow < NN)
                    ? *(const float4*)(A + (size_t)arow * 512 + k0 + lc4[p] * 4)
                    : make_float4(0.f, 0.f, 0.f, 0.f);
                ra[p] = cvt_tf32x4(av);
                float4 bv = *(const float4*)(g_W12t + (size_t)(colBase + lrow[p]) * 512 + k0 + lc4[p] * 4);
                rb[p] = cvt_tf32x4(bv);
            }
        }
#pragma unroll
        for (int ks = 0; ks < 4; ks++) {
            const int kb = ks * 8 + tq;
            uint32_t af[4][4];
#pragma unroll
            for (int mt = 0; mt < 4; mt++) {
                int base = (wr * 64 + mt * 16 + gq) * SPAD + kb;
                af[mt][0] = sA[base];
                af[mt][1] = sA[base + 8 * SPAD];
                af[mt][2] = sA[base + 4];
                af[mt][3] = sA[base + 8 * SPAD + 4];
            }
            uint32_t bf[4][2];
#pragma unroll
            for (int nt = 0; nt < 4; nt++) {
                int base = (wc * 32 + nt * 8 + gq) * SPAD + kb;
                bf[nt][0] = sB[base];
                bf[nt][1] = sB[base + 4];
            }
#pragma unroll
            for (int mt = 0; mt < 4; mt++)
#pragma unroll
                for (int nt = 0; nt < 4; nt++)
                    MMA_TF32(c[mt][nt], af[mt], bf[nt]);
        }
        __syncthreads();
        if (it + 1 < 16) {
#pragma unroll
            for (int p = 0; p < 4; p++) {
                *(uint4*)&sA[lrow[p] * SPAD + lc4[p] * 4] = ra[p];
                *(uint4*)&sB[lrow[p] * SPAD + lc4[p] * 4] = rb[p];
            }
            __syncthreads();
        }
    }

    // epilogue
#pragma unroll
    for (int mt = 0; mt < 4; mt++) {
        int row0 = rowBase + wr * 64 + mt * 16 + gq;
#pragma unroll
        for (int nt = 0; nt < 4; nt++) {
            int col = colBase + wc * 32 + nt * 8 + tq * 2;
            if (row0 < NN) {
                float2 v0 = { c[mt][nt][0], c[mt][nt][1] };
                *(float2*)(g_h + (size_t)row0 * 512 + col) = v0;
            }
            if (row0 + 8 < NN) {
                float2 v1 = { c[mt][nt][2], c[mt][nt][3] };
                *(float2*)(g_h + (size_t)(row0 + 8) * 512 + col) = v1;
            }
        }
    }
}

// ---------------- small helpers ----------------
__global__ void zero_cc() {
    int i = blockIdx.x * blockDim.x + threadIdx.x;
    if (i < DC * 128) { g_kinc[i] = 0.0f; g_vinc[i] = 0.0f; }
}

__global__ void pack2(float* __restrict__ W, const float* __restrict__ W1,
                      const float* __restrict__ W2, float* __restrict__ b,
                      const float* __restrict__ b1, const float* __restrict__ b2,
                      int rows, int hc) {
    int idx = blockIdx.x * blockDim.x + threadIdx.x;
    int tot = rows * 2 * hc;
    if (idx < tot) {
        int r = idx / (2 * hc);
        int c = idx - r * 2 * hc;
        W[idx] = (c < hc) ? W1[r * hc + c] : W2[r * hc + (c - hc)];
    }
    if (idx < 2 * hc) b[idx] = (idx < hc) ? b1[idx] : b2[idx - hc];
}

// transposed fused pack: W12t[n][k] = [gcn_W | gcnA2_W][k][n]
__global__ void pack_w12t(const float* __restrict__ gcn_W, const float* __restrict__ gcnA2_W,
                          const float* __restrict__ gcn_b, const float* __restrict__ gcnA2_b) {
    int idx = blockIdx.x * blockDim.x + threadIdx.x;
    if (idx < 512 * 512) {
        int n = idx >> 9;
        int k = idx & 511;
        g_W12t[idx] = (n < 256) ? gcn_W[k * 256 + n] : gcnA2_W[k * 256 + (n - 256)];
    }
    if (idx < 512) g_b12[idx] = (idx < 256) ? gcn_b[idx] : gcnA2_b[idx - 256];
}

// ---------------- CSR construction ----------------
__global__ void deg_zero() {
    int i = blockIdx.x * blockDim.x + threadIdx.x;
    if (i < NN) { g_deg[i] = 0; g_cnt[i] = 0; }
}
__global__ void deg_count(const int* __restrict__ adj) {
    int e = blockIdx.x * blockDim.x + threadIdx.x;
    if (e < EE) atomicAdd(&g_deg[adj[EE + e]], 1);
}
__global__ void __launch_bounds__(1024) scan_offsets() {
    __shared__ int partial[1024];
    const int tid = threadIdx.x;
    const int PER = (NN + 1023) / 1024;
    const int base = tid * PER;
    int s = 0;
#pragma unroll
    for (int i = 0; i < PER; i++) {
        int idx = base + i;
        if (idx < NN) s += g_deg[idx];
    }
    partial[tid] = s;
    __syncthreads();
    for (int off = 1; off < 1024; off <<= 1) {
        int v = 0;
        if (tid >= off) v = partial[tid - off];
        __syncthreads();
        if (tid >= off) partial[tid] += v;
        __syncthreads();
    }
    int run = (tid > 0) ? partial[tid - 1] : 0;
#pragma unroll
    for (int i = 0; i < PER; i++) {
        int idx = base + i;
        if (idx < NN) {
            g_off[idx] = run;
            int d = g_deg[idx];
            run += d;
            g_dinv[idx] = rsqrtf(1.0f + (float)d);
        }
    }
    if (tid == 0) g_off[NN] = EE;
}
__global__ void fill_csr(const int* __restrict__ adj) {
    int e = blockIdx.x * blockDim.x + threadIdx.x;
    if (e >= EE) return;
    int s = adj[e];
    int d = adj[EE + e];
    int pos = g_off[d] + atomicAdd(&g_cnt[d], 1);
    g_esrc[pos] = s;
}

// ---------------- row sums of Ek / Ev ----------------
__global__ void rowsums(const float* __restrict__ Ek, const float* __restrict__ Ev) {
    int gw = (blockIdx.x * blockDim.x + threadIdx.x) >> 5;
    int lane = threadIdx.x & 31;
    if (gw >= 2 * DC) return;
    const float* src = (gw < DC) ? Ek + (size_t)gw * NN : Ev + (size_t)(gw - DC) * NN;
    float s = 0.0f;
    for (int i = lane * 4; i < NN; i += 128) {
        float4 v = *(const float4*)(src + i);
        s += v.x + v.y + v.z + v.w;
    }
#pragma unroll
    for (int o = 16; o > 0; o >>= 1) s += __shfl_xor_sync(0xffffffffu, s, o);
    if (lane == 0) {
        if (gw < DC) g_rsk[gw] = s;
        else         g_rsv[gw - DC] = s;
    }
}

// ---------------- CSR gather + fused GCN finalize --------------------------
__global__ void __launch_bounds__(128) gcn_gather() {
    __shared__ int   s_src[128];
    __shared__ float s_coef[128];
    const int d = blockIdx.x;
    const int tid = threadIdx.x;
    const int beg = g_off[d];
    const int deg = g_off[d + 1] - beg;
    const float di = g_dinv[d];

    float4 acc = {0.f, 0.f, 0.f, 0.f};
    for (int c0 = 0; c0 < deg; c0 += 128) {
        int m = min(128, deg - c0);
        if (tid < m) {
            int s = g_esrc[beg + c0 + tid];
            s_src[tid] = s;
            s_coef[tid] = g_dinv[s] * di;
        }
        __syncthreads();
        int i = 0;
#pragma unroll 1
        for (; i + 4 <= m; i += 4) {
            const float4 h0 = *(const float4*)(g_h + (size_t)s_src[i + 0] * 512 + tid * 4);
            const float4 h1 = *(const float4*)(g_h + (size_t)s_src[i + 1] * 512 + tid * 4);
            const float4 h2 = *(const float4*)(g_h + (size_t)s_src[i + 2] * 512 + tid * 4);
            const float4 h3 = *(const float4*)(g_h + (size_t)s_src[i + 3] * 512 + tid * 4);
            float c0f = s_coef[i + 0], c1f = s_coef[i + 1];
            float c2f = s_coef[i + 2], c3f = s_coef[i + 3];
            acc.x += h0.x * c0f; acc.y += h0.y * c0f; acc.z += h0.z * c0f; acc.w += h0.w * c0f;
            acc.x += h1.x * c1f; acc.y += h1.y * c1f; acc.z += h1.z * c1f; acc.w += h1.w * c1f;
            acc.x += h2.x * c2f; acc.y += h2.y * c2f; acc.z += h2.z * c2f; acc.w += h2.w * c2f;
            acc.x += h3.x * c3f; acc.y += h3.y * c3f; acc.z += h3.z * c3f; acc.w += h3.w * c3f;
        }
        for (; i < m; i++) {
            const float4 hv = *(const float4*)(g_h + (size_t)s_src[i] * 512 + tid * 4);
            float cf = s_coef[i];
            acc.x += hv.x * cf; acc.y += hv.y * cf; acc.z += hv.z * cf; acc.w += hv.w * cf;
        }
        __syncthreads();
    }

    const int j = tid * 4;
    const float4 hd = *(const float4*)(g_h + (size_t)d * 512 + j);
    const float4 bb = *(const float4*)(g_b12 + j);
    const float d2 = di * di;
    float4 v;
    v.x = acc.x + hd.x * d2 + bb.x;
    v.y = acc.y + hd.y * d2 + bb.y;
    v.z = acc.z + hd.z * d2 + bb.z;
    v.w = acc.w + hd.w * d2 + bb.w;
    if (j < 256) {
        float4 o;
        o.x = 1.0f / (1.0f + __expf(-v.x));
        o.y = 1.0f / (1.0f + __expf(-v.y));
        o.z = 1.0f / (1.0f + __expf(-v.z));
        o.w = 1.0f / (1.0f + __expf(-v.w));
        *(float4*)(g_g1 + (size_t)d * 256 + j) = o;
    } else {
        *(float4*)(g_xa + (size_t)d * 256 + (j - 256)) = v;
    }
}

// ---------------- kin = tf + pos_emb[positions] ----------------------------
__global__ void build_kin(const int* __restrict__ positions,
                          const float* __restrict__ pos_emb) {
    int idx = blockIdx.x * blockDim.x + threadIdx.x;
    if (idx >= NN * 128) return;
    int n = idx >> 7;
    int j = idx & 127;
    g_kin[idx] = g_tftg[(size_t)n * 256 + j] + pos_emb[positions[n] * 128 + j];
}

// ---------------- SGEMM: C = act(A@B + bias) -------------------------------
// BM=BN=128, BK=16, double-buffered smem, 256 threads, 8x8 per thread.
template <int ACT>
__global__ void __launch_bounds__(256)
sgemm2(const float* __restrict__ A, const float* __restrict__ B,
       const float* __restrict__ bias, const float* __restrict__ rowscale,
       float* __restrict__ C, int M, int N, int K) {
    __shared__ float As[2][16][128];
    __shared__ float Bs[2][16][128];
    const int tid = threadIdx.x;
    const int rowBase = blockIdx.y * 128;
    const int colBase = blockIdx.x * 128;

    const int lr = tid >> 1;
    const int lq = (tid & 1) * 8;
    const int br = tid >> 5;
    const int bc = (tid & 31) * 4;
    const int rm = tid >> 4;
    const int rn = tid & 15;

    const int arow = rowBase + lr;
    const bool aval = arow < M;
    const float* Aptr = A + (size_t)arow * K + lq;
    const float* Bptr = B + colBase + bc;

    float acc[8][8];
#pragma unroll
    for (int i = 0; i < 8; i++)
#pragma unroll
        for (int j = 0; j < 8; j++) acc[i][j] = 0.0f;

    const int niter = K >> 4;
    float4 a0, a1, b0, b1;
    a0 = aval ? *(const float4*)(Aptr + 0) : make_float4(0, 0, 0, 0);
    a1 = aval ? *(const float4*)(Aptr + 4) : make_float4(0, 0, 0, 0);
    b0 = *(const float4*)(Bptr + (size_t)br * N);
    b1 = *(const float4*)(Bptr + (size_t)(br + 8) * N);
    As[0][lq + 0][lr] = a0.x; As[0][lq + 1][lr] = a0.y;
    As[0][lq + 2][lr] = a0.z; As[0][lq + 3][lr] = a0.w;
    As[0][lq + 4][lr] = a1.x; As[0][lq + 5][lr] = a1.y;
    As[0][lq + 6][lr] = a1.z; As[0][lq + 7][lr] = a1.w;
    *(float4*)&Bs[0][br][bc] = b0;
    *(float4*)&Bs[0][br + 8][bc] = b1;
    __syncthreads();

    for (int it = 0; it < niter; it++) {
        const int cur = it & 1;
        if (it + 1 < niter) {
            const int k0 = (it + 1) << 4;
            a0 = aval ? *(const float4*)(Aptr + k0) : make_float4(0, 0, 0, 0);
            a1 = aval ? *(const float4*)(Aptr + k0 + 4) : make_float4(0, 0, 0, 0);
            b0 = *(const float4*)(Bptr + (size_t)(k0 + br) * N);
            b1 = *(const float4*)(Bptr + (size_t)(k0 + br + 8) * N);
        }
#pragma unroll
        for (int k = 0; k < 16; k++) {
            float4 av0 = *(const float4*)&As[cur][k][rm * 8];
            float4 av1 = *(const float4*)&As[cur][k][rm * 8 + 4];
            float4 bv0 = *(const float4*)&Bs[cur][k][rn * 8];
            float4 bv1 = *(const float4*)&Bs[cur][k][rn * 8 + 4];
            float av[8] = {av0.x, av0.y, av0.z, av0.w, av1.x, av1.y, av1.z, av1.w};
            float bv[8] = {bv0.x, bv0.y, bv0.z, bv0.w, bv1.x, bv1.y, bv1.z, bv1.w};
#pragma unroll
            for (int i = 0; i < 8; i++)
#pragma unroll
                for (int j = 0; j < 8; j++) acc[i][j] += av[i] * bv[j];
        }
        if (it + 1 < niter) {
            const int nxt = cur ^ 1;
            As[nxt][lq + 0][lr] = a0.x; As[nxt][lq + 1][lr] = a0.y;
            As[nxt][lq + 2][lr] = a0.z; As[nxt][lq + 3][lr] = a0.w;
            As[nxt][lq + 4][lr] = a1.x; As[nxt][lq + 5][lr] = a1.y;
            As[nxt][lq + 6][lr] = a1.z; As[nxt][lq + 7][lr] = a1.w;
            *(float4*)&Bs[nxt][br][bc] = b0;
            *(float4*)&Bs[nxt][br + 8][bc] = b1;
        }
        __syncthreads();
    }

#pragma unroll
    for (int i = 0; i < 8; i++) {
        int row = rowBase + rm * 8 + i;
        if (row >= M) continue;
        float rsc = (ACT == 2) ? rowscale[row] : 1.0f;
        int col0 = colBase + rn * 8;
#pragma unroll
        for (int j4 = 0; j4 < 2; j4++) {
            float4 o;
            float* op = &o.x;
#pragma unroll
            for (int j = 0; j < 4; j++) {
                int jj = j4 * 4 + j;
                float v = acc[i][jj];
                if (bias) v += rsc * bias[col0 + jj];
                if (ACT == 1) v = (v >= 0.0f) ? v : 0.01f * v;
                op[j] = v;
            }
            *(float4*)&C[(size_t)row * N + col0 + j4 * 4] = o;
        }
    }
}

// ---------------- split-K GEMM: kinc = Ek@kin, vinc = Ev@tg ----------------
__global__ void __launch_bounds__(256)
splitk_ckv(const float* __restrict__ Ekm, const float* __restrict__ Evm) {
    const int mat = blockIdx.z & 1;
    const int split = blockIdx.z >> 1;
    const float* Am = mat ? Evm : Ekm;
    const float* Xm = mat ? (g_tftg + 128) : g_kin;
    const int ldb = mat ? 256 : 128;
    float* Cm = mat ? g_vinc : g_kinc;

    const int rowBase = blockIdx.y * 64;
    const int colBase = blockIdx.x * 64;
    const int tid = threadIdx.x;
    const int rm = tid >> 4, rn = tid & 15;

    __shared__ float As[32][64];
    __shared__ float Bs[32][64];

    float acc[4][4];
#pragma unroll
    for (int i = 0; i < 4; i++)
#pragma unroll
        for (int j = 0; j < 4; j++) acc[i][j] = 0.0f;

    const int kstart = split * 25 * 32;
    for (int it = 0; it < 25; it++) {
        int kbase = kstart + it * 32;
        __syncthreads();
#pragma unroll
        for (int pp = 0; pp < 2; pp++) {
            int p = tid + pp * 256;
            int row = p >> 3;
            int kq = (p & 7) * 4;
            float4 a4 = *(const float4*)(Am + (size_t)(rowBase + row) * NN + kbase + kq);
            As[kq + 0][row] = a4.x;
            As[kq + 1][row] = a4.y;
            As[kq + 2][row] = a4.z;
            As[kq + 3][row] = a4.w;
            int krow = p >> 4;
            int cq = (p & 15) * 4;
            float4 b4 = *(const float4*)(Xm + (size_t)(kbase + krow) * ldb + colBase + cq);
            *(float4*)&Bs[krow][cq] = b4;
        }
        __syncthreads();
#pragma unroll
        for (int k = 0; k < 32; k++) {
            float4 a4 = *(float4*)&As[k][rm * 4];
            float4 b4 = *(float4*)&Bs[k][rn * 4];
            float av[4] = {a4.x, a4.y, a4.z, a4.w};
            float bv[4] = {b4.x, b4.y, b4.z, b4.w};
#pragma unroll
            for (int i = 0; i < 4; i++)
#pragma unroll
                for (int j = 0; j < 4; j++) acc[i][j] += av[i] * bv[j];
        }
    }
#pragma unroll
    for (int i = 0; i < 4; i++)
#pragma unroll
        for (int j = 0; j < 4; j++)
            atomicAdd(&Cm[(size_t)(rowBase + rm * 4 + i) * 128 + colBase + rn * 4 + j],
                      acc[i][j]);
}

// ---------------- fused attention (plain softmax) --------------------------
__global__ void __launch_bounds__(128)
attn_kernel(const int* __restrict__ positions) {
    __shared__ float4 kcs[DC][4];
    __shared__ float4 vcs[DC][4];
    const int h = blockIdx.y;
    const int tid = threadIdx.x;
    for (int p = tid; p < DC * 4; p += 128) {
        int c = p >> 2, d = p & 3;
        kcs[c][d] = *(const float4*)(g_kc + c * 128 + h * 16 + d * 4);
        vcs[c][d] = *(const float4*)(g_vc + c * 128 + h * 16 + d * 4);
    }
    __syncthreads();
    int n = blockIdx.x * 128 + tid;
    if (n >= NN) return;

    const int pos = positions[n];
    const float* qp = g_q + (size_t)n * 128 + h * 16;
    const float* pp = g_peq + (size_t)pos * 128 + h * 16;
    float4 q0 = *(const float4*)(qp + 0);
    float4 q1 = *(const float4*)(qp + 4);
    float4 q2 = *(const float4*)(qp + 8);
    float4 q3 = *(const float4*)(qp + 12);
    float4 p0 = *(const float4*)(pp + 0);
    float4 p1 = *(const float4*)(pp + 4);
    float4 p2 = *(const float4*)(pp + 8);
    float4 p3 = *(const float4*)(pp + 12);
    q0.x += p0.x; q0.y += p0.y; q0.z += p0.z; q0.w += p0.w;
    q1.x += p1.x; q1.y += p1.y; q1.z += p1.z; q1.w += p1.w;
    q2.x += p2.x; q2.y += p2.y; q2.z += p2.z; q2.w += p2.w;
    q3.x += p3.x; q3.y += p3.y; q3.z += p3.z; q3.w += p3.w;

    float s = 0.0f;
    float4 o0 = {0, 0, 0, 0}, o1 = {0, 0, 0, 0}, o2 = {0, 0, 0, 0}, o3 = {0, 0, 0, 0};

    for (int c = 0; c < DC; c++) {
        float4 k0 = kcs[c][0], k1 = kcs[c][1], k2 = kcs[c][2], k3 = kcs[c][3];
        float dot = q0.x * k0.x + q0.y * k0.y + q0.z * k0.z + q0.w * k0.w
                  + q1.x * k1.x + q1.y * k1.y + q1.z * k1.z + q1.w * k1.w
                  + q2.x * k2.x + q2.y * k2.y + q2.z * k2.z + q2.w * k2.w
                  + q3.x * k3.x + q3.y * k3.y + q3.z * k3.z + q3.w * k3.w;
        float p = __expf(dot * 0.25f);
        s += p;
        float4 v0 = vcs[c][0], v1 = vcs[c][1], v2 = vcs[c][2], v3 = vcs[c][3];
        o0.x += p * v0.x; o0.y += p * v0.y; o0.z += p * v0.z; o0.w += p * v0.w;
        o1.x += p * v1.x; o1.y += p * v1.y; o1.z += p * v1.z; o1.w += p * v1.w;
        o2.x += p * v2.x; o2.y += p * v2.y; o2.z += p * v2.z; o2.w += p * v2.w;
        o3.x += p * v3.x; o3.y += p * v3.y; o3.z += p * v3.z; o3.w += p * v3.w;
    }
    float inv = 1.0f / s;
    float* op = g_att + (size_t)n * 128 + h * 16;
    o0.x *= inv; o0.y *= inv; o0.z *= inv; o0.w *= inv;
    o1.x *= inv; o1.y *= inv; o1.z *= inv; o1.w *= inv;
    o2.x *= inv; o2.y *= inv; o2.z *= inv; o2.w *= inv;
    o3.x *= inv; o3.y *= inv; o3.z *= inv; o3.w *= inv;
    *(float4*)(op + 0) = o0;
    *(float4*)(op + 4) = o1;
    *(float4*)(op + 8) = o2;
    *(float4*)(op + 12) = o3;
}

// ---------------- row norms of tfa / tga ----------------
__global__ void norms_kernel() {
    int n = blockIdx.x * blockDim.x + threadIdx.x;
    if (n >= NN) return;
    const float4* a = (const float4*)(g_ab + (size_t)n * 128);
    float sa = 0.0f, sb = 0.0f;
#pragma unroll
    for (int i = 0; i < 16; i++) {
        float4 v = a[i];
        sa += v.x * v.x + v.y * v.y + v.z * v.z + v.w * v.w;
    }
#pragma unroll
    for (int i = 16; i < 32; i++) {
        float4 v = a[i];
        sb += v.x * v.x + v.y * v.y + v.z * v.z + v.w * v.w;
    }
    g_na[n] = sqrtf(sa);
    g_nb[n] = sqrtf(sb);
}

// ---------------- final cosine for 200K pairs ----------------
__global__ void final_pairs(const int* __restrict__ ts, float* __restrict__ out) {
    int t = blockIdx.x * blockDim.x + threadIdx.x;
    if (t >= NT) return;
    int i = ts[2 * t];
    int j = ts[2 * t + 1];
    const float4* a = (const float4*)(g_ab + (size_t)i * 128);
    const float4* b = (const float4*)(g_ab + (size_t)j * 128 + 64);
    float dot = 0.0f;
#pragma unroll
    for (int p = 0; p < 16; p++) {
        float4 av = a[p];
        float4 bv = b[p];
        dot += av.x * bv.x + av.y * bv.y + av.z * bv.z + av.w * bv.w;
    }
    out[t] = dot / fmaxf(g_na[i] * g_nb[j], 1e-8f);
}

// ---------------- host launcher ----------------
static float* symaddr(const void* sym) {
    void* p = nullptr;
    cudaGetSymbolAddress(&p, sym);
    return (float*)p;
}

extern "C" void kernel_launch(void* const* d_in, const int* in_sizes, int n_in,
                              void* d_out, int out_size) {
    const int*   train_sample = (const int*)d_in[1];
    const float* data_feature = (const float*)d_in[2];
    const int*   adj          = (const int*)d_in[3];
    const int*   positions    = (const int*)d_in[4];
    const float* gcn_W   = (const float*)d_in[5];
    const float* gcn_b   = (const float*)d_in[6];
    const float* gcnA2_W = (const float*)d_in[7];
    const float* gcnA2_b = (const float*)d_in[8];
    const float* lin_W   = (const float*)d_in[9];
    const float* lin_b   = (const float*)d_in[10];
    const float* tf_W    = (const float*)d_in[11];
    const float* tf_b    = (const float*)d_in[12];
    const float* tg_W    = (const float*)d_in[13];
    const float* tg_b    = (const float*)d_in[14];
    const float* Wq = (const float*)d_in[15];
    const float* bq = (const float*)d_in[16];
    const float* Wk = (const float*)d_in[17];
    const float* bk = (const float*)d_in[18];
    const float* Wv = (const float*)d_in[19];
    const float* bv = (const float*)d_in[20];
    const float* Wo = (const float*)d_in[21];
    const float* bo = (const float*)d_in[22];
    const float* Ek = (const float*)d_in[23];
    const float* Ev = (const float*)d_in[24];
    const float* pos_emb = (const float*)d_in[25];
    const float* tfa_W = (const float*)d_in[26];
    const float* tfa_b = (const float*)d_in[27];
    const float* tga_W = (const float*)d_in[28];
    const float* tga_b = (const float*)d_in[29];

    float* d_Wtftg = symaddr(g_Wtftg);
    float* d_btftg = symaddr(g_btftg);
    float* d_Wab   = symaddr(g_Wab);
    float* d_bab   = symaddr(g_bab);
    float* d_g1   = symaddr(g_g1);
    float* d_xa   = symaddr(g_xa);
    float* d_xg   = symaddr(g_xg);
    float* d_tftg = symaddr(g_tftg);
    float* d_q    = symaddr(g_q);
    float* d_peq  = symaddr(g_peq);
    float* d_kinc = symaddr(g_kinc);
    float* d_vinc = symaddr(g_vinc);
    float* d_rsk  = symaddr(g_rsk);
    float* d_rsv  = symaddr(g_rsv);
    float* d_kc   = symaddr(g_kc);
    float* d_vc   = symaddr(g_vc);
    float* d_att  = symaddr(g_att);
    float* d_xf   = symaddr(g_xf);
    float* d_ab   = symaddr(g_ab);

    // 1. pack fused weight blocks (W12 transposed for mma B operand)
    pack_w12t<<<(512 * 512 + 255) / 256, 256>>>(gcn_W, gcnA2_W, gcn_b, gcnA2_b);
    pack2<<<(256 * 256 + 255) / 256, 256>>>(d_Wtftg, tf_W, tg_W, d_btftg, tf_b, tg_b, 256, 128);
    pack2<<<(128 * 128 + 255) / 256, 256>>>(d_Wab, tfa_W, tga_W, d_bab, tfa_b, tga_b, 128, 64);

    // 2. CSR construction + Ek/Ev row sums
    deg_zero<<<(NN + 255) / 256, 256>>>();
    deg_count<<<(EE + 255) / 256, 256>>>(adj);
    scan_offsets<<<1, 1024>>>();
    fill_csr<<<(EE + 255) / 256, 256>>>(adj);
    rowsums<<<(2 * DC * 32 + 255) / 256, 256>>>(Ek, Ev);

    // 3. h = data_feature @ [gcn_W | gcnA2_W]  — tf32 mma.sync tensor cores
    mma_h<<<dim3(4, 157), 256>>>(data_feature);

    // 4. CSR gather + fused finalize -> g1 (sigmoid), xa
    gcn_gather<<<NN, 128>>>();

    // 5. x_g = leaky(g1 @ lin_W + lin_b); [tf|tg] = leaky(xa @ [tf_W|tg_W] + b)
    sgemm2<1><<<dim3(1, 157), 256>>>(d_g1, lin_W, lin_b, nullptr, d_xg, NN, 128, 256);
    sgemm2<1><<<dim3(2, 157), 256>>>(d_xa, d_Wtftg, d_btftg, nullptr, d_tftg, NN, 256, 256);

    // 6. q = xg@Wq + bq; peq = pos_emb@Wq; kin = tf + pe
    sgemm2<0><<<dim3(1, 157), 256>>>(d_xg, Wq, bq, nullptr, d_q, NN, 128, 128);
    sgemm2<0><<<dim3(1, 4), 256>>>(pos_emb, Wq, nullptr, nullptr, d_peq, 512, 128, 128);
    build_kin<<<(NN * 128 + 255) / 256, 256>>>(positions, pos_emb);

    // 7. kinc = Ek@kin, vinc = Ev@tg (split-K), then project at DC scale
    zero_cc<<<(DC * 128 + 255) / 256, 256>>>();
    splitk_ckv<<<dim3(2, 4, 50), 256>>>(Ek, Ev);
    sgemm2<2><<<dim3(1, 2), 256>>>(d_kinc, Wk, bk, d_rsk, d_kc, DC, 128, 128);
    sgemm2<2><<<dim3(1, 2), 256>>>(d_vinc, Wv, bv, d_rsv, d_vc, DC, 128, 128);

    // 8. fused attention
    attn_kernel<<<dim3(157, HEADS), 128>>>(positions);

    // 9. x_f = att @ Wo + bo; [tfa|tga] = leaky(x_f @ [tfa_W|tga_W] + b)
    sgemm2<0><<<dim3(1, 157), 256>>>(d_att, Wo, bo, nullptr, d_xf, NN, 128, 128);
    sgemm2<1><<<dim3(1, 157), 256>>>(d_xf, d_Wab, d_bab, nullptr, d_ab, NN, 128, 128);

    // 10. norms + final cosine pairs
    norms_kernel<<<(NN + 255) / 256, 256>>>();
    final_pairs<<<(NT + 255) / 256, 256>>>(train_sample, (float*)d_out);
}

// round 12
// speedup vs baseline: 1.5034x; 1.0905x over previous
#include <cuda_runtime.h>
#include <math.h>
#include <stdint.h>

// ---------------- problem constants ----------------
constexpr int NN   = 20000;
constexpr int EE   = 320000;
constexpr int NT   = 200000;
constexpr int DC   = 256;
constexpr int HEADS = 8;

// ---------------- scratch (static device globals; no runtime alloc) --------
__device__ float g_W12t[512 * 512];        // transposed fused weights [n][k]
__device__ float g_b12[512];
__device__ float g_lint[128 * 256];        // lin_W^T
__device__ float g_tftgt[256 * 256];       // [tf_W | tg_W]^T
__device__ float g_btftg[256];
__device__ float g_Wqt[128 * 128];
__device__ float g_Wot[128 * 128];
__device__ float g_abt[128 * 128];         // [tfa_W | tga_W]^T
__device__ float g_bab[128];

__device__ float g_h[(size_t)NN * 512];    // [h_gcn1 | h_gcn2]
__device__ float g_dinv[NN];

__device__ int g_deg[NN];
__device__ int g_cnt[NN];
__device__ int g_off[NN + 1];
__device__ int g_esrc[EE];

__device__ float g_g1[(size_t)NN * 256];
__device__ float g_xa[(size_t)NN * 256];
__device__ float g_xg[(size_t)NN * 128];
__device__ float g_tftg[(size_t)NN * 256];

__device__ float g_kin[(size_t)NN * 128];
__device__ float g_q[(size_t)NN * 128];
__device__ float g_peq[512 * 128];

__device__ float g_kinc[DC * 128];
__device__ float g_vinc[DC * 128];
__device__ float g_rsk[DC];
__device__ float g_rsv[DC];
__device__ float g_kc[DC * 128];
__device__ float g_vc[DC * 128];

__device__ float g_att[(size_t)NN * 128];
__device__ float g_xf[(size_t)NN * 128];
__device__ float g_ab[(size_t)NN * 128];
__device__ float g_na[NN];
__device__ float g_nb[NN];

// ---------------- tf32 helpers ----------------
__device__ __forceinline__ uint32_t cvt_tf32(float f) {
    uint32_t u;
    asm("cvt.rna.tf32.f32 %0, %1;" : "=r"(u) : "f"(f));
    return u;
}
__device__ __forceinline__ uint4 cvt_tf32x4(float4 v) {
    uint4 r;
    r.x = cvt_tf32(v.x); r.y = cvt_tf32(v.y);
    r.z = cvt_tf32(v.z); r.w = cvt_tf32(v.w);
    return r;
}
#define MMA_TF32(c, a, b) \
    asm volatile( \
        "mma.sync.aligned.m16n8k8.row.col.f32.tf32.tf32.f32 " \
        "{%0,%1,%2,%3}, {%4,%5,%6,%7}, {%8,%9}, {%0,%1,%2,%3};" \
        : "+f"((c)[0]), "+f"((c)[1]), "+f"((c)[2]), "+f"((c)[3]) \
        : "r"((a)[0]), "r"((a)[1]), "r"((a)[2]), "r"((a)[3]), \
          "r"((b)[0]), "r"((b)[1]))

// ---------------- generic tf32 mma.sync GEMM: C = act(A@Bt^T + bias) -------
// BM=128, BN=128, BK=32. 256 threads = 8 warps; warp tile 64x32 (4x4 m16n8k8).
// A: [M][K] row-major fp32.  Bt: [N][K] row-major fp32 (i.e. B transposed).
// N multiple of 128 (grid.x = N/128), K multiple of 32. M tail-guarded.
// ACT: 0 = none, 1 = leaky relu.
constexpr int SPAD = 36;  // smem row stride in words (conflict-free frags)
template <int ACT>
__global__ void __launch_bounds__(256)
mma_gemm(const float* __restrict__ A, const float* __restrict__ Bt,
         const float* __restrict__ bias, float* __restrict__ C,
         int M, int N, int K) {
    __shared__ uint32_t sA[128 * SPAD];
    __shared__ uint32_t sB[128 * SPAD];
    const int tid = threadIdx.x;
    const int lane = tid & 31, wid = tid >> 5;
    const int wr = wid >> 2, wc = wid & 3;       // warp row (0..1) / col (0..3)
    const int gq = lane >> 2, tq = lane & 3;     // group / thread-in-group
    const int rowBase = blockIdx.y * 128;
    const int colBase = blockIdx.x * 128;

    float c[4][4][4];
#pragma unroll
    for (int mt = 0; mt < 4; mt++)
#pragma unroll
        for (int nt = 0; nt < 4; nt++)
#pragma unroll
            for (int r = 0; r < 4; r++) c[mt][nt][r] = 0.0f;

    int lrow[4], lc4[4];
#pragma unroll
    for (int p = 0; p < 4; p++) {
        int idx = tid + p * 256;
        lrow[p] = idx >> 3;
        lc4[p] = idx & 7;
    }

    uint4 ra[4], rb[4];
    // preload iter 0
#pragma unroll
    for (int p = 0; p < 4; p++) {
        int arow = rowBase + lrow[p];
        float4 av = (arow < M)
            ? *(const float4*)(A + (size_t)arow * K + lc4[p] * 4)
            : make_float4(0.f, 0.f, 0.f, 0.f);
        ra[p] = cvt_tf32x4(av);
        float4 bv = *(const float4*)(Bt + (size_t)(colBase + lrow[p]) * K + lc4[p] * 4);
        rb[p] = cvt_tf32x4(bv);
    }
#pragma unroll
    for (int p = 0; p < 4; p++) {
        *(uint4*)&sA[lrow[p] * SPAD + lc4[p] * 4] = ra[p];
        *(uint4*)&sB[lrow[p] * SPAD + lc4[p] * 4] = rb[p];
    }
    __syncthreads();

    const int niter = K >> 5;
    for (int it = 0; it < niter; it++) {
        if (it + 1 < niter) {
            const int k0 = (it + 1) * 32;
#pragma unroll
            for (int p = 0; p < 4; p++) {
                int arow = rowBase + lrow[p];
                float4 av = (arow < M)
                    ? *(const float4*)(A + (size_t)arow * K + k0 + lc4[p] * 4)
                    : make_float4(0.f, 0.f, 0.f, 0.f);
                ra[p] = cvt_tf32x4(av);
                float4 bv = *(const float4*)(Bt + (size_t)(colBase + lrow[p]) * K + k0 + lc4[p] * 4);
                rb[p] = cvt_tf32x4(bv);
            }
        }
#pragma unroll
        for (int ks = 0; ks < 4; ks++) {
            const int kb = ks * 8 + tq;
            uint32_t af[4][4];
#pragma unroll
            for (int mt = 0; mt < 4; mt++) {
                int base = (wr * 64 + mt * 16 + gq) * SPAD + kb;
                af[mt][0] = sA[base];
                af[mt][1] = sA[base + 8 * SPAD];
                af[mt][2] = sA[base + 4];
                af[mt][3] = sA[base + 8 * SPAD + 4];
            }
            uint32_t bf[4][2];
#pragma unroll
            for (int nt = 0; nt < 4; nt++) {
                int base = (wc * 32 + nt * 8 + gq) * SPAD + kb;
                bf[nt][0] = sB[base];
                bf[nt][1] = sB[base + 4];
            }
#pragma unroll
            for (int mt = 0; mt < 4; mt++)
#pragma unroll
                for (int nt = 0; nt < 4; nt++)
                    MMA_TF32(c[mt][nt], af[mt], bf[nt]);
        }
        __syncthreads();
        if (it + 1 < niter) {
#pragma unroll
            for (int p = 0; p < 4; p++) {
                *(uint4*)&sA[lrow[p] * SPAD + lc4[p] * 4] = ra[p];
                *(uint4*)&sB[lrow[p] * SPAD + lc4[p] * 4] = rb[p];
            }
            __syncthreads();
        }
    }

    // epilogue: bias + activation
#pragma unroll
    for (int mt = 0; mt < 4; mt++) {
        int row0 = rowBase + wr * 64 + mt * 16 + gq;
#pragma unroll
        for (int nt = 0; nt < 4; nt++) {
            int col = colBase + wc * 32 + nt * 8 + tq * 2;
            float b0 = 0.f, b1 = 0.f;
            if (bias) {
                float2 bb = *(const float2*)(bias + col);
                b0 = bb.x; b1 = bb.y;
            }
            float v0 = c[mt][nt][0] + b0, v1 = c[mt][nt][1] + b1;
            float v2 = c[mt][nt][2] + b0, v3 = c[mt][nt][3] + b1;
            if (ACT == 1) {
                v0 = (v0 >= 0.f) ? v0 : 0.01f * v0;
                v1 = (v1 >= 0.f) ? v1 : 0.01f * v1;
                v2 = (v2 >= 0.f) ? v2 : 0.01f * v2;
                v3 = (v3 >= 0.f) ? v3 : 0.01f * v3;
            }
            if (row0 < M) {
                float2 o = { v0, v1 };
                *(float2*)(C + (size_t)row0 * N + col) = o;
            }
            if (row0 + 8 < M) {
                float2 o = { v2, v3 };
                *(float2*)(C + (size_t)(row0 + 8) * N + col) = o;
            }
        }
    }
}

// ---------------- small helpers ----------------
__global__ void zero_cc() {
    int i = blockIdx.x * blockDim.x + threadIdx.x;
    if (i < DC * 128) { g_kinc[i] = 0.0f; g_vinc[i] = 0.0f; }
}

// generic transpose: Wt[n*K + k] = W[k*N + n]   (W is [K][N])
__global__ void transpose_w(float* __restrict__ Wt, const float* __restrict__ W,
                            int N, int K) {
    int idx = blockIdx.x * blockDim.x + threadIdx.x;
    if (idx >= N * K) return;
    int n = idx / K;
    int k = idx - n * K;
    Wt[idx] = W[k * N + n];
}

// fused transposed pair pack: Wt[n][k] = n<hc ? W1[k][n] : W2[k][n-hc]
// W1, W2 are [K][hc]. Also packs bias pair.
__global__ void pack2t(float* __restrict__ Wt, const float* __restrict__ W1,
                       const float* __restrict__ W2, float* __restrict__ b,
                       const float* __restrict__ b1, const float* __restrict__ b2,
                       int hc, int K) {
    int idx = blockIdx.x * blockDim.x + threadIdx.x;
    int tot = 2 * hc * K;
    if (idx < tot) {
        int n = idx / K;
        int k = idx - n * K;
        Wt[idx] = (n < hc) ? W1[k * hc + n] : W2[k * hc + (n - hc)];
    }
    if (idx < 2 * hc) b[idx] = (idx < hc) ? b1[idx] : b2[idx - hc];
}

// transposed fused pack for the big weights: W12t[n][k]
__global__ void pack_w12t(const float* __restrict__ gcn_W, const float* __restrict__ gcnA2_W,
                          const float* __restrict__ gcn_b, const float* __restrict__ gcnA2_b) {
    int idx = blockIdx.x * blockDim.x + threadIdx.x;
    if (idx < 512 * 512) {
        int n = idx >> 9;
        int k = idx & 511;
        g_W12t[idx] = (n < 256) ? gcn_W[k * 256 + n] : gcnA2_W[k * 256 + (n - 256)];
    }
    if (idx < 512) g_b12[idx] = (idx < 256) ? gcn_b[idx] : gcnA2_b[idx - 256];
}

// ---------------- CSR construction ----------------
__global__ void deg_zero() {
    int i = blockIdx.x * blockDim.x + threadIdx.x;
    if (i < NN) { g_deg[i] = 0; g_cnt[i] = 0; }
}
__global__ void deg_count(const int* __restrict__ adj) {
    int e = blockIdx.x * blockDim.x + threadIdx.x;
    if (e < EE) atomicAdd(&g_deg[adj[EE + e]], 1);
}
__global__ void __launch_bounds__(1024) scan_offsets() {
    __shared__ int partial[1024];
    const int tid = threadIdx.x;
    const int PER = (NN + 1023) / 1024;
    const int base = tid * PER;
    int s = 0;
#pragma unroll
    for (int i = 0; i < PER; i++) {
        int idx = base + i;
        if (idx < NN) s += g_deg[idx];
    }
    partial[tid] = s;
    __syncthreads();
    for (int off = 1; off < 1024; off <<= 1) {
        int v = 0;
        if (tid >= off) v = partial[tid - off];
        __syncthreads();
        if (tid >= off) partial[tid] += v;
        __syncthreads();
    }
    int run = (tid > 0) ? partial[tid - 1] : 0;
#pragma unroll
    for (int i = 0; i < PER; i++) {
        int idx = base + i;
        if (idx < NN) {
            g_off[idx] = run;
            int d = g_deg[idx];
            run += d;
            g_dinv[idx] = rsqrtf(1.0f + (float)d);
        }
    }
    if (tid == 0) g_off[NN] = EE;
}
__global__ void fill_csr(const int* __restrict__ adj) {
    int e = blockIdx.x * blockDim.x + threadIdx.x;
    if (e >= EE) return;
    int s = adj[e];
    int d = adj[EE + e];
    int pos = g_off[d] + atomicAdd(&g_cnt[d], 1);
    g_esrc[pos] = s;
}

// ---------------- row sums of Ek / Ev ----------------
__global__ void rowsums(const float* __restrict__ Ek, const float* __restrict__ Ev) {
    int gw = (blockIdx.x * blockDim.x + threadIdx.x) >> 5;
    int lane = threadIdx.x & 31;
    if (gw >= 2 * DC) return;
    const float* src = (gw < DC) ? Ek + (size_t)gw * NN : Ev + (size_t)(gw - DC) * NN;
    float s = 0.0f;
    for (int i = lane * 4; i < NN; i += 128) {
        float4 v = *(const float4*)(src + i);
        s += v.x + v.y + v.z + v.w;
    }
#pragma unroll
    for (int o = 16; o > 0; o >>= 1) s += __shfl_xor_sync(0xffffffffu, s, o);
    if (lane == 0) {
        if (gw < DC) g_rsk[gw] = s;
        else         g_rsv[gw - DC] = s;
    }
}

// ---------------- CSR gather + fused GCN finalize --------------------------
__global__ void __launch_bounds__(128) gcn_gather() {
    __shared__ int   s_src[128];
    __shared__ float s_coef[128];
    const int d = blockIdx.x;
    const int tid = threadIdx.x;
    const int beg = g_off[d];
    const int deg = g_off[d + 1] - beg;
    const float di = g_dinv[d];

    float4 acc = {0.f, 0.f, 0.f, 0.f};
    for (int c0 = 0; c0 < deg; c0 += 128) {
        int m = min(128, deg - c0);
        if (tid < m) {
            int s = g_esrc[beg + c0 + tid];
            s_src[tid] = s;
            s_coef[tid] = g_dinv[s] * di;
        }
        __syncthreads();
        int i = 0;
#pragma unroll 1
        for (; i + 4 <= m; i += 4) {
            const float4 h0 = *(const float4*)(g_h + (size_t)s_src[i + 0] * 512 + tid * 4);
            const float4 h1 = *(const float4*)(g_h + (size_t)s_src[i + 1] * 512 + tid * 4);
            const float4 h2 = *(const float4*)(g_h + (size_t)s_src[i + 2] * 512 + tid * 4);
            const float4 h3 = *(const float4*)(g_h + (size_t)s_src[i + 3] * 512 + tid * 4);
            float c0f = s_coef[i + 0], c1f = s_coef[i + 1];
            float c2f = s_coef[i + 2], c3f = s_coef[i + 3];
            acc.x += h0.x * c0f; acc.y += h0.y * c0f; acc.z += h0.z * c0f; acc.w += h0.w * c0f;
            acc.x += h1.x * c1f; acc.y += h1.y * c1f; acc.z += h1.z * c1f; acc.w += h1.w * c1f;
            acc.x += h2.x * c2f; acc.y += h2.y * c2f; acc.z += h2.z * c2f; acc.w += h2.w * c2f;
            acc.x += h3.x * c3f; acc.y += h3.y * c3f; acc.z += h3.z * c3f; acc.w += h3.w * c3f;
        }
        for (; i < m; i++) {
            const float4 hv = *(const float4*)(g_h + (size_t)s_src[i] * 512 + tid * 4);
            float cf = s_coef[i];
            acc.x += hv.x * cf; acc.y += hv.y * cf; acc.z += hv.z * cf; acc.w += hv.w * cf;
        }
        __syncthreads();
    }

    const int j = tid * 4;
    const float4 hd = *(const float4*)(g_h + (size_t)d * 512 + j);
    const float4 bb = *(const float4*)(g_b12 + j);
    const float d2 = di * di;
    float4 v;
    v.x = acc.x + hd.x * d2 + bb.x;
    v.y = acc.y + hd.y * d2 + bb.y;
    v.z = acc.z + hd.z * d2 + bb.z;
    v.w = acc.w + hd.w * d2 + bb.w;
    if (j < 256) {
        float4 o;
        o.x = 1.0f / (1.0f + __expf(-v.x));
        o.y = 1.0f / (1.0f + __expf(-v.y));
        o.z = 1.0f / (1.0f + __expf(-v.z));
        o.w = 1.0f / (1.0f + __expf(-v.w));
        *(float4*)(g_g1 + (size_t)d * 256 + j) = o;
    } else {
        *(float4*)(g_xa + (size_t)d * 256 + (j - 256)) = v;
    }
}

// ---------------- kin = tf + pos_emb[positions] ----------------------------
__global__ void build_kin(const int* __restrict__ positions,
                          const float* __restrict__ pos_emb) {
    int idx = blockIdx.x * blockDim.x + threadIdx.x;
    if (idx >= NN * 128) return;
    int n = idx >> 7;
    int j = idx & 127;
    g_kin[idx] = g_tftg[(size_t)n * 256 + j] + pos_emb[positions[n] * 128 + j];
}

// ---------------- SGEMM (SIMT, small launches only) ------------------------
// BM=BN=128, BK=16, double-buffered smem, 256 threads, 8x8 per thread.
template <int ACT>
__global__ void __launch_bounds__(256)
sgemm2(const float* __restrict__ A, const float* __restrict__ B,
       const float* __restrict__ bias, const float* __restrict__ rowscale,
       float* __restrict__ C, int M, int N, int K) {
    __shared__ float As[2][16][128];
    __shared__ float Bs[2][16][128];
    const int tid = threadIdx.x;
    const int rowBase = blockIdx.y * 128;
    const int colBase = blockIdx.x * 128;

    const int lr = tid >> 1;
    const int lq = (tid & 1) * 8;
    const int br = tid >> 5;
    const int bc = (tid & 31) * 4;
    const int rm = tid >> 4;
    const int rn = tid & 15;

    const int arow = rowBase + lr;
    const bool aval = arow < M;
    const float* Aptr = A + (size_t)arow * K + lq;
    const float* Bptr = B + colBase + bc;

    float acc[8][8];
#pragma unroll
    for (int i = 0; i < 8; i++)
#pragma unroll
        for (int j = 0; j < 8; j++) acc[i][j] = 0.0f;

    const int niter = K >> 4;
    float4 a0, a1, b0, b1;
    a0 = aval ? *(const float4*)(Aptr + 0) : make_float4(0, 0, 0, 0);
    a1 = aval ? *(const float4*)(Aptr + 4) : make_float4(0, 0, 0, 0);
    b0 = *(const float4*)(Bptr + (size_t)br * N);
    b1 = *(const float4*)(Bptr + (size_t)(br + 8) * N);
    As[0][lq + 0][lr] = a0.x; As[0][lq + 1][lr] = a0.y;
    As[0][lq + 2][lr] = a0.z; As[0][lq + 3][lr] = a0.w;
    As[0][lq + 4][lr] = a1.x; As[0][lq + 5][lr] = a1.y;
    As[0][lq + 6][lr] = a1.z; As[0][lq + 7][lr] = a1.w;
    *(float4*)&Bs[0][br][bc] = b0;
    *(float4*)&Bs[0][br + 8][bc] = b1;
    __syncthreads();

    for (int it = 0; it < niter; it++) {
        const int cur = it & 1;
        if (it + 1 < niter) {
            const int k0 = (it + 1) << 4;
            a0 = aval ? *(const float4*)(Aptr + k0) : make_float4(0, 0, 0, 0);
            a1 = aval ? *(const float4*)(Aptr + k0 + 4) : make_float4(0, 0, 0, 0);
            b0 = *(const float4*)(Bptr + (size_t)(k0 + br) * N);
            b1 = *(const float4*)(Bptr + (size_t)(k0 + br + 8) * N);
        }
#pragma unroll
        for (int k = 0; k < 16; k++) {
            float4 av0 = *(const float4*)&As[cur][k][rm * 8];
            float4 av1 = *(const float4*)&As[cur][k][rm * 8 + 4];
            float4 bv0 = *(const float4*)&Bs[cur][k][rn * 8];
            float4 bv1 = *(const float4*)&Bs[cur][k][rn * 8 + 4];
            float av[8] = {av0.x, av0.y, av0.z, av0.w, av1.x, av1.y, av1.z, av1.w};
            float bv[8] = {bv0.x, bv0.y, bv0.z, bv0.w, bv1.x, bv1.y, bv1.z, bv1.w};
#pragma unroll
            for (int i = 0; i < 8; i++)
#pragma unroll
                for (int j = 0; j < 8; j++) acc[i][j] += av[i] * bv[j];
        }
        if (it + 1 < niter) {
            const int nxt = cur ^ 1;
            As[nxt][lq + 0][lr] = a0.x; As[nxt][lq + 1][lr] = a0.y;
            As[nxt][lq + 2][lr] = a0.z; As[nxt][lq + 3][lr] = a0.w;
            As[nxt][lq + 4][lr] = a1.x; As[nxt][lq + 5][lr] = a1.y;
            As[nxt][lq + 6][lr] = a1.z; As[nxt][lq + 7][lr] = a1.w;
            *(float4*)&Bs[nxt][br][bc] = b0;
            *(float4*)&Bs[nxt][br + 8][bc] = b1;
        }
        __syncthreads();
    }

#pragma unroll
    for (int i = 0; i < 8; i++) {
        int row = rowBase + rm * 8 + i;
        if (row >= M) continue;
        float rsc = (ACT == 2) ? rowscale[row] : 1.0f;
        int col0 = colBase + rn * 8;
#pragma unroll
        for (int j4 = 0; j4 < 2; j4++) {
            float4 o;
            float* op = &o.x;
#pragma unroll
            for (int j = 0; j < 4; j++) {
                int jj = j4 * 4 + j;
                float v = acc[i][jj];
                if (bias) v += rsc * bias[col0 + jj];
                if (ACT == 1) v = (v >= 0.0f) ? v : 0.01f * v;
                op[j] = v;
            }
            *(float4*)&C[(size_t)row * N + col0 + j4 * 4] = o;
        }
    }
}

// ---------------- split-K GEMM: kinc = Ek@kin, vinc = Ev@tg ----------------
__global__ void __launch_bounds__(256)
splitk_ckv(const float* __restrict__ Ekm, const float* __restrict__ Evm) {
    const int mat = blockIdx.z & 1;
    const int split = blockIdx.z >> 1;
    const float* Am = mat ? Evm : Ekm;
    const float* Xm = mat ? (g_tftg + 128) : g_kin;
    const int ldb = mat ? 256 : 128;
    float* Cm = mat ? g_vinc : g_kinc;

    const int rowBase = blockIdx.y * 64;
    const int colBase = blockIdx.x * 64;
    const int tid = threadIdx.x;
    const int rm = tid >> 4, rn = tid & 15;

    __shared__ float As[32][64];
    __shared__ float Bs[32][64];

    float acc[4][4];
#pragma unroll
    for (int i = 0; i < 4; i++)
#pragma unroll
        for (int j = 0; j < 4; j++) acc[i][j] = 0.0f;

    const int kstart = split * 25 * 32;
    for (int it = 0; it < 25; it++) {
        int kbase = kstart + it * 32;
        __syncthreads();
#pragma unroll
        for (int pp = 0; pp < 2; pp++) {
            int p = tid + pp * 256;
            int row = p >> 3;
            int kq = (p & 7) * 4;
            float4 a4 = *(const float4*)(Am + (size_t)(rowBase + row) * NN + kbase + kq);
            As[kq + 0][row] = a4.x;
            As[kq + 1][row] = a4.y;
            As[kq + 2][row] = a4.z;
            As[kq + 3][row] = a4.w;
            int krow = p >> 4;
            int cq = (p & 15) * 4;
            float4 b4 = *(const float4*)(Xm + (size_t)(kbase + krow) * ldb + colBase + cq);
            *(float4*)&Bs[krow][cq] = b4;
        }
        __syncthreads();
#pragma unroll
        for (int k = 0; k < 32; k++) {
            float4 a4 = *(float4*)&As[k][rm * 4];
            float4 b4 = *(float4*)&Bs[k][rn * 4];
            float av[4] = {a4.x, a4.y, a4.z, a4.w};
            float bv[4] = {b4.x, b4.y, b4.z, b4.w};
#pragma unroll
            for (int i = 0; i < 4; i++)
#pragma unroll
                for (int j = 0; j < 4; j++) acc[i][j] += av[i] * bv[j];
        }
    }
#pragma unroll
    for (int i = 0; i < 4; i++)
#pragma unroll
        for (int j = 0; j < 4; j++)
            atomicAdd(&Cm[(size_t)(rowBase + rm * 4 + i) * 128 + colBase + rn * 4 + j],
                      acc[i][j]);
}

// ---------------- fused attention (plain softmax) --------------------------
__global__ void __launch_bounds__(128)
attn_kernel(const int* __restrict__ positions) {
    __shared__ float4 kcs[DC][4];
    __shared__ float4 vcs[DC][4];
    const int h = blockIdx.y;
    const int tid = threadIdx.x;
    for (int p = tid; p < DC * 4; p += 128) {
        int c = p >> 2, d = p & 3;
        kcs[c][d] = *(const float4*)(g_kc + c * 128 + h * 16 + d * 4);
        vcs[c][d] = *(const float4*)(g_vc + c * 128 + h * 16 + d * 4);
    }
    __syncthreads();
    int n = blockIdx.x * 128 + tid;
    if (n >= NN) return;

    const int pos = positions[n];
    const float* qp = g_q + (size_t)n * 128 + h * 16;
    const float* pp = g_peq + (size_t)pos * 128 + h * 16;
    float4 q0 = *(const float4*)(qp + 0);
    float4 q1 = *(const float4*)(qp + 4);
    float4 q2 = *(const float4*)(qp + 8);
    float4 q3 = *(const float4*)(qp + 12);
    float4 p0 = *(const float4*)(pp + 0);
    float4 p1 = *(const float4*)(pp + 4);
    float4 p2 = *(const float4*)(pp + 8);
    float4 p3 = *(const float4*)(pp + 12);
    q0.x += p0.x; q0.y += p0.y; q0.z += p0.z; q0.w += p0.w;
    q1.x += p1.x; q1.y += p1.y; q1.z += p1.z; q1.w += p1.w;
    q2.x += p2.x; q2.y += p2.y; q2.z += p2.z; q2.w += p2.w;
    q3.x += p3.x; q3.y += p3.y; q3.z += p3.z; q3.w += p3.w;

    float s = 0.0f;
    float4 o0 = {0, 0, 0, 0}, o1 = {0, 0, 0, 0}, o2 = {0, 0, 0, 0}, o3 = {0, 0, 0, 0};

    for (int c = 0; c < DC; c++) {
        float4 k0 = kcs[c][0], k1 = kcs[c][1], k2 = kcs[c][2], k3 = kcs[c][3];
        float dot = q0.x * k0.x + q0.y * k0.y + q0.z * k0.z + q0.w * k0.w
                  + q1.x * k1.x + q1.y * k1.y + q1.z * k1.z + q1.w * k1.w
                  + q2.x * k2.x + q2.y * k2.y + q2.z * k2.z + q2.w * k2.w
                  + q3.x * k3.x + q3.y * k3.y + q3.z * k3.z + q3.w * k3.w;
        float p = __expf(dot * 0.25f);
        s += p;
        float4 v0 = vcs[c][0], v1 = vcs[c][1], v2 = vcs[c][2], v3 = vcs[c][3];
        o0.x += p * v0.x; o0.y += p * v0.y; o0.z += p * v0.z; o0.w += p * v0.w;
        o1.x += p * v1.x; o1.y += p * v1.y; o1.z += p * v1.z; o1.w += p * v1.w;
        o2.x += p * v2.x; o2.y += p * v2.y; o2.z += p * v2.z; o2.w += p * v2.w;
        o3.x += p * v3.x; o3.y += p * v3.y; o3.z += p * v3.z; o3.w += p * v3.w;
    }
    float inv = 1.0f / s;
    float* op = g_att + (size_t)n * 128 + h * 16;
    o0.x *= inv; o0.y *= inv; o0.z *= inv; o0.w *= inv;
    o1.x *= inv; o1.y *= inv; o1.z *= inv; o1.w *= inv;
    o2.x *= inv; o2.y *= inv; o2.z *= inv; o2.w *= inv;
    o3.x *= inv; o3.y *= inv; o3.z *= inv; o3.w *= inv;
    *(float4*)(op + 0) = o0;
    *(float4*)(op + 4) = o1;
    *(float4*)(op + 8) = o2;
    *(float4*)(op + 12) = o3;
}

// ---------------- row norms of tfa / tga ----------------
__global__ void norms_kernel() {
    int n = blockIdx.x * blockDim.x + threadIdx.x;
    if (n >= NN) return;
    const float4* a = (const float4*)(g_ab + (size_t)n * 128);
    float sa = 0.0f, sb = 0.0f;
#pragma unroll
    for (int i = 0; i < 16; i++) {
        float4 v = a[i];
        sa += v.x * v.x + v.y * v.y + v.z * v.z + v.w * v.w;
    }
#pragma unroll
    for (int i = 16; i < 32; i++) {
        float4 v = a[i];
        sb += v.x * v.x + v.y * v.y + v.z * v.z + v.w * v.w;
    }
    g_na[n] = sqrtf(sa);
    g_nb[n] = sqrtf(sb);
}

// ---------------- final cosine for 200K pairs ----------------
__global__ void final_pairs(const int* __restrict__ ts, float* __restrict__ out) {
    int t = blockIdx.x * blockDim.x + threadIdx.x;
    if (t >= NT) return;
    int i = ts[2 * t];
    int j = ts[2 * t + 1];
    const float4* a = (const float4*)(g_ab + (size_t)i * 128);
    const float4* b = (const float4*)(g_ab + (size_t)j * 128 + 64);
    float dot = 0.0f;
#pragma unroll
    for (int p = 0; p < 16; p++) {
        float4 av = a[p];
        float4 bv = b[p];
        dot += av.x * bv.x + av.y * bv.y + av.z * bv.z + av.w * bv.w;
    }
    out[t] = dot / fmaxf(g_na[i] * g_nb[j], 1e-8f);
}

// ---------------- host launcher ----------------
static float* symaddr(const void* sym) {
    void* p = nullptr;
    cudaGetSymbolAddress(&p, sym);
    return (float*)p;
}

extern "C" void kernel_launch(void* const* d_in, const int* in_sizes, int n_in,
                              void* d_out, int out_size) {
    const int*   train_sample = (const int*)d_in[1];
    const float* data_feature = (const float*)d_in[2];
    const int*   adj          = (const int*)d_in[3];
    const int*   positions    = (const int*)d_in[4];
    const float* gcn_W   = (const float*)d_in[5];
    const float* gcn_b   = (const float*)d_in[6];
    const float* gcnA2_W = (const float*)d_in[7];
    const float* gcnA2_b = (const float*)d_in[8];
    const float* lin_W   = (const float*)d_in[9];
    const float* lin_b   = (const float*)d_in[10];
    const float* tf_W    = (const float*)d_in[11];
    const float* tf_b    = (const float*)d_in[12];
    const float* tg_W    = (const float*)d_in[13];
    const float* tg_b    = (const float*)d_in[14];
    const float* Wq = (const float*)d_in[15];
    const float* bq = (const float*)d_in[16];
    const float* Wk = (const float*)d_in[17];
    const float* bk = (const float*)d_in[18];
    const float* Wv = (const float*)d_in[19];
    const float* bv = (const float*)d_in[20];
    const float* Wo = (const float*)d_in[21];
    const float* bo = (const float*)d_in[22];
    const float* Ek = (const float*)d_in[23];
    const float* Ev = (const float*)d_in[24];
    const float* pos_emb = (const float*)d_in[25];
    const float* tfa_W = (const float*)d_in[26];
    const float* tfa_b = (const float*)d_in[27];
    const float* tga_W = (const float*)d_in[28];
    const float* tga_b = (const float*)d_in[29];

    float* d_W12t  = symaddr(g_W12t);
    float* d_lint  = symaddr(g_lint);
    float* d_tftgt = symaddr(g_tftgt);
    float* d_btftg = symaddr(g_btftg);
    float* d_Wqt   = symaddr(g_Wqt);
    float* d_Wot   = symaddr(g_Wot);
    float* d_abt   = symaddr(g_abt);
    float* d_bab   = symaddr(g_bab);
    float* d_g1   = symaddr(g_g1);
    float* d_xa   = symaddr(g_xa);
    float* d_xg   = symaddr(g_xg);
    float* d_tftg = symaddr(g_tftg);
    float* d_q    = symaddr(g_q);
    float* d_peq  = symaddr(g_peq);
    float* d_kinc = symaddr(g_kinc);
    float* d_vinc = symaddr(g_vinc);
    float* d_rsk  = symaddr(g_rsk);
    float* d_rsv  = symaddr(g_rsv);
    float* d_kc   = symaddr(g_kc);
    float* d_vc   = symaddr(g_vc);
    float* d_att  = symaddr(g_att);
    float* d_xf   = symaddr(g_xf);
    float* d_ab   = symaddr(g_ab);
    float* d_h    = symaddr(g_h);

    // 1. weight packs (all transposed for mma B operand)
    pack_w12t<<<(512 * 512 + 255) / 256, 256>>>(gcn_W, gcnA2_W, gcn_b, gcnA2_b);
    transpose_w<<<(128 * 256 + 255) / 256, 256>>>(d_lint, lin_W, 128, 256);
    pack2t<<<(256 * 256 + 255) / 256, 256>>>(d_tftgt, tf_W, tg_W, d_btftg, tf_b, tg_b, 128, 256);
    transpose_w<<<(128 * 128 + 255) / 256, 256>>>(d_Wqt, Wq, 128, 128);
    transpose_w<<<(128 * 128 + 255) / 256, 256>>>(d_Wot, Wo, 128, 128);
    pack2t<<<(128 * 128 + 255) / 256, 256>>>(d_abt, tfa_W, tga_W, d_bab, tfa_b, tga_b, 64, 128);

    // 2. CSR construction + Ek/Ev row sums
    deg_zero<<<(NN + 255) / 256, 256>>>();
    deg_count<<<(EE + 255) / 256, 256>>>(adj);
    scan_offsets<<<1, 1024>>>();
    fill_csr<<<(EE + 255) / 256, 256>>>(adj);
    rowsums<<<(2 * DC * 32 + 255) / 256, 256>>>(Ek, Ev);

    // 3. h = data_feature @ [gcn_W | gcnA2_W]  — tf32 mma
    mma_gemm<0><<<dim3(4, 157), 256>>>(data_feature, d_W12t, nullptr, d_h, NN, 512, 512);

    // 4. CSR gather + fused finalize -> g1 (sigmoid), xa
    gcn_gather<<<NN, 128>>>();

    // 5. x_g = leaky(g1 @ lin_W + b); [tf|tg] = leaky(xa @ [tf_W|tg_W] + b)  — tf32 mma
    mma_gemm<1><<<dim3(1, 157), 256>>>(d_g1, d_lint, lin_b, d_xg, NN, 128, 256);
    mma_gemm<1><<<dim3(2, 157), 256>>>(d_xa, d_tftgt, d_btftg, d_tftg, NN, 256, 256);

    // 6. q = xg@Wq + bq (mma); peq = pos_emb@Wq (SIMT, tiny); kin = tf + pe
    mma_gemm<0><<<dim3(1, 157), 256>>>(d_xg, d_Wqt, bq, d_q, NN, 128, 128);
    sgemm2<0><<<dim3(1, 4), 256>>>(pos_emb, Wq, nullptr, nullptr, d_peq, 512, 128, 128);
    build_kin<<<(NN * 128 + 255) / 256, 256>>>(positions, pos_emb);

    // 7. kinc = Ek@kin, vinc = Ev@tg (split-K), then project at DC scale
    zero_cc<<<(DC * 128 + 255) / 256, 256>>>();
    splitk_ckv<<<dim3(2, 4, 50), 256>>>(Ek, Ev);
    sgemm2<2><<<dim3(1, 2), 256>>>(d_kinc, Wk, bk, d_rsk, d_kc, DC, 128, 128);
    sgemm2<2><<<dim3(1, 2), 256>>>(d_vinc, Wv, bv, d_rsv, d_vc, DC, 128, 128);

    // 8. fused attention
    attn_kernel<<<dim3(157, HEADS), 128>>>(positions);

    // 9. x_f = att@Wo + bo; [tfa|tga] = leaky(x_f@[tfa_W|tga_W] + b) — tf32 mma
    mma_gemm<0><<<dim3(1, 157), 256>>>(d_att, d_Wot, bo, d_xf, NN, 128, 128);
    mma_gemm<1><<<dim3(1, 157), 256>>>(d_xf, d_abt, d_bab, d_ab, NN, 128, 128);

    // 10. norms + final cosine pairs
    norms_kernel<<<(NN + 255) / 256, 256>>>();
    final_pairs<<<(NT + 255) / 256, 256>>>(train_sample, (float*)d_out);
}